// round 13
// baseline (speedup 1.0000x reference)
#include <cuda_runtime.h>
#include <cuda_bf16.h>
#include <cstdint>
#include <math.h>
#include <float.h>

#define BB   4
#define NN   4096
#define DD   1024
#define WW   128
#define NWIN (NN / WW)          // 32
#define MTOT (BB * NN)          // 16384

// ---------------------------------------------------------------------------
// bf16 hi/lo split scratch. ONLY referenced from device code — NEVER passed
// as kernel args from host (host-side &symbol is the shadow copy; GB300 ATS
// makes writes to it silently land in host memory).
// ---------------------------------------------------------------------------
__device__ __nv_bfloat16 g_x_hi  [(size_t)MTOT * DD];
__device__ __nv_bfloat16 g_x_lo  [(size_t)MTOT * DD];
__device__ __nv_bfloat16 g_wqk_hi[(size_t)2048 * DD];   // [n][k] = w_qkv[k][n]
__device__ __nv_bfloat16 g_wqk_lo[(size_t)2048 * DD];
__device__ __nv_bfloat16 g_wo_hi [(size_t)1024 * DD];   // [n][k] = w_out[k][n]
__device__ __nv_bfloat16 g_wo_lo [(size_t)1024 * DD];
__device__ __nv_bfloat16 g_q_hi  [(size_t)MTOT * DD];
__device__ __nv_bfloat16 g_q_lo  [(size_t)MTOT * DD];
__device__ __nv_bfloat16 g_k_hi  [(size_t)MTOT * DD];
__device__ __nv_bfloat16 g_k_lo  [(size_t)MTOT * DD];
__device__ __nv_bfloat16 g_kT_hi [(size_t)BB * DD * NN]; // [b][d][t]
__device__ __nv_bfloat16 g_kT_lo [(size_t)BB * DD * NN];
__device__ __nv_bfloat16 g_attn_hi[(size_t)MTOT * 256];  // unnormalized exp
__device__ __nv_bfloat16 g_attn_lo[(size_t)MTOT * 256];
__device__ __nv_bfloat16 g_ao_hi [(size_t)MTOT * DD];
__device__ __nv_bfloat16 g_ao_lo [(size_t)MTOT * DD];
__device__ float         g_invsum[MTOT];
// zero source for masked cp.async (device globals are zero-initialized)
__device__ __align__(16) __nv_bfloat16 g_zero[16];

// ---------------------------------------------------------------------------
// primitives
// ---------------------------------------------------------------------------
__device__ __forceinline__ uint32_t smem_u32(const void* p) {
    uint32_t a;
    asm("{ .reg .u64 t; cvta.to.shared.u64 t, %1; cvt.u32.u64 %0, t; }"
        : "=r"(a) : "l"(p));
    return a;
}

__device__ __forceinline__ void mma16816(float* c, const uint32_t* a, const uint32_t* b) {
    asm volatile(
        "mma.sync.aligned.m16n8k16.row.col.f32.bf16.bf16.f32 "
        "{%0,%1,%2,%3}, {%4,%5,%6,%7}, {%8,%9}, {%0,%1,%2,%3};"
        : "+f"(c[0]), "+f"(c[1]), "+f"(c[2]), "+f"(c[3])
        : "r"(a[0]), "r"(a[1]), "r"(a[2]), "r"(a[3]), "r"(b[0]), "r"(b[1]));
}

__device__ __forceinline__ void ldsm_x4(uint32_t& d0, uint32_t& d1,
                                        uint32_t& d2, uint32_t& d3, uint32_t a) {
    asm volatile("ldmatrix.sync.aligned.m8n8.x4.shared.b16 {%0,%1,%2,%3}, [%4];"
                 : "=r"(d0), "=r"(d1), "=r"(d2), "=r"(d3) : "r"(a));
}

__device__ __forceinline__ void cp16(uint32_t dst, const void* src) {
    asm volatile("cp.async.cg.shared.global [%0], [%1], 16;"
                 :: "r"(dst), "l"(src) : "memory");
}

// mbarrier machinery (sm_80-class; NOT tcgen05)
#define MBAR_INIT(a, cnt) \
    asm volatile("mbarrier.init.shared.b64 [%0], %1;" :: "r"(a), "r"(cnt) : "memory")
#define MBAR_ARRIVE(a) \
    asm volatile("mbarrier.arrive.shared.b64 _, [%0];" :: "r"(a) : "memory")
#define CPA_MBAR_ARRIVE(a) \
    asm volatile("cp.async.mbarrier.arrive.noinc.shared.b64 [%0];" :: "r"(a) : "memory")
#define MBAR_WAIT(a, parity) do {                                              \
    asm volatile(                                                              \
        "{\n\t.reg .pred P1;\n"                                                \
        "WAIT_LOOP_%=:\n\t"                                                    \
        "mbarrier.try_wait.parity.acquire.cta.shared::cta.b64 P1, [%0], %1, 0x989680;\n\t" \
        "@P1 bra.uni WAIT_DONE_%=;\n\t"                                        \
        "bra.uni WAIT_LOOP_%=;\n"                                              \
        "WAIT_DONE_%=:\n\t}"                                                   \
        :: "r"(a), "r"(parity) : "memory");                                    \
} while (0)

__device__ __forceinline__ void f2bf_split(float v, __nv_bfloat16& hi, __nv_bfloat16& lo) {
    hi = __float2bfloat16(v);
    lo = __float2bfloat16(v - __bfloat162float(hi));
}

// smem per buffer: K-chunk 32 -> 64B data + 16B pad = 80B row stride.
//   A_hi [128][80] @ 0      (10240 B)   A_lo @ 10240
//   B_hi [256][80] @ 20480  (20480 B)   B_lo @ 40960
#define RS    80
#define A_HI  0
#define A_LO  10240
#define B_HI  20480
#define B_LO  40960
#define BUFB  61440
#define NBUF  3
#define MBAR_OFF (NBUF * BUFB)        // 184320: full[3] then empty[3], 8B each
#define SMEMB (NBUF * BUFB + 64)      // 184384; stg 128*257*4=131584 aliases bufs
#define NT    512                     // 16 warps: 4x4 warp grid, warp tile 32x64

// ---------------------------------------------------------------------------
// async chunk loader (A[128]x32 + B[256]x32, hi+lo); masked segs read g_zero
// 512 threads: A = 1 seg/thread, B = 2 segs/thread (hi+lo each)
// ---------------------------------------------------------------------------
__device__ __forceinline__ void load_chunk_async(
    uint32_t smb, int cc, int bufIdx, int stage, int w, int t,
    const __nv_bfloat16* Ah, const __nv_bfloat16* Al,
    const __nv_bfloat16* Bh, const __nv_bfloat16* Bl,
    long long aBase, long long bBase, int Astr, int Bstr)
{
    const int kE = cc * 32;
    const uint32_t bo = (uint32_t)bufIdx * BUFB;
    // A: 128 rows x 4 segs of 16B = 512 segs
    {
        const int r = t >> 2, sg = t & 3;
        const long long off = aBase + (long long)r * Astr + kE + sg * 8;
        const uint32_t d = smb + bo + A_HI + r * RS + sg * 16;
        cp16(d, Ah + off);
        cp16(d + (A_LO - A_HI), Al + off);
    }
    // B: 256 rows x 4 segs of 16B = 1024 segs
    #pragma unroll
    for (int i = 0; i < 2; i++) {
        const int idx = t + i * NT;
        const int r = idx >> 2, sg = idx & 3;
        bool v = true;
        if (stage == 1) v = (w > 0) || (r >= 128);
        if (stage == 2) v = (w > 0) || (cc >= 4);
        const int o = B_HI + r * RS + sg * 16;
        const long long off = bBase + (long long)r * Bstr + kE + sg * 8;
        const __nv_bfloat16* sh = v ? (Bh + off) : g_zero;
        const __nv_bfloat16* sl = v ? (Bl + off) : g_zero;
        cp16(smb + bo + o, sh);
        cp16(smb + bo + o + (B_LO - B_HI), sl);
    }
}

// ---------------------------------------------------------------------------
// one K-chunk (k=32, two k16 steps): bf16x3 (AhBh + AhBl + AlBh) via ldmatrix
// warp tile 32x64: A frags 2, B frags 8
// ---------------------------------------------------------------------------
__device__ __forceinline__ void compute_chunk(
    uint32_t bufAdd, const uint32_t* aAddr, const uint32_t* bAddr,
    float (&acc)[2][8][4])
{
    #pragma unroll
    for (int kk = 0; kk < 2; kk++) {
        const uint32_t kb = bufAdd + (uint32_t)kk * 32u;
        uint32_t A[2][4], B0[8][2], B1[8][2];
        #pragma unroll
        for (int fm = 0; fm < 2; fm++)
            ldsm_x4(A[fm][0], A[fm][1], A[fm][2], A[fm][3], aAddr[fm] + kb);
        #pragma unroll
        for (int p = 0; p < 4; p++)
            ldsm_x4(B0[2*p][0], B0[2*p][1], B0[2*p+1][0], B0[2*p+1][1],
                    bAddr[p] + kb);
        #pragma unroll
        for (int fm = 0; fm < 2; fm++)
            #pragma unroll
            for (int fn = 0; fn < 8; fn++)
                mma16816(acc[fm][fn], A[fm], B0[fn]);    // Ah*Bh
        #pragma unroll
        for (int p = 0; p < 4; p++)
            ldsm_x4(B1[2*p][0], B1[2*p][1], B1[2*p+1][0], B1[2*p+1][1],
                    bAddr[p] + kb + (B_LO - B_HI));
        #pragma unroll
        for (int fm = 0; fm < 2; fm++)
            #pragma unroll
            for (int fn = 0; fn < 8; fn++)
                mma16816(acc[fm][fn], A[fm], B1[fn]);    // Ah*Bl
        #pragma unroll
        for (int fm = 0; fm < 2; fm++)
            ldsm_x4(A[fm][0], A[fm][1], A[fm][2], A[fm][3],
                    aAddr[fm] + kb + (A_LO - A_HI));
        #pragma unroll
        for (int fm = 0; fm < 2; fm++)
            #pragma unroll
            for (int fn = 0; fn < 8; fn++)
                mma16816(acc[fm][fn], A[fm], B0[fn]);    // Al*Bh
    }
}

// ---------------------------------------------------------------------------
// Unified GEMM: D[128,256] = A[128,K] @ B[256,K]^T via mma.sync bf16x3.
// mbarrier-ring pipeline (no per-chunk __syncthreads): warps slide freely.
// stage 0: QKV   A=x        B=wqkT        K=1024  epi: split into g_q / g_k
// stage 1: QK^T  A=q(win)   B=k(win-1,w)  K=1024  epi: softmax -> attn+invsum
// stage 2: A*V   A=attn     B=kT          K=256   epi: *invsum -> g_ao
// stage 3: OUT   A=ao       B=woT         K=1024  epi: +bias -> d_out (fp32)
// ---------------------------------------------------------------------------
__global__ void __launch_bounds__(NT, 1) mma_gemm(int stage,
                                                  float* __restrict__ dOut,
                                                  const float* __restrict__ bias)
{
    extern __shared__ char sm[];
    const uint32_t smb = smem_u32(sm);
    const uint32_t mbF = smb + MBAR_OFF;       // full[3] @ +0, empty[3] @ +24
    const uint32_t mbE = mbF + 24;
    const int t = threadIdx.x;
    const int lane = t & 31, wid = t >> 5;
    const int wm = wid & 3, wn = wid >> 2;     // 4 M-slices x 4 N-slices
    const int g = lane >> 2, tg = lane & 3;

    int m0 = 0, n0 = 0, b = 0, w = 0;
    if (stage == 0)      { n0 = blockIdx.x * 256; m0 = blockIdx.y * 128; }
    else if (stage == 1) { w = blockIdx.x; b = blockIdx.y; }
    else if (stage == 2) { n0 = blockIdx.x * 256; w = blockIdx.y; b = blockIdx.z; }
    else                 { n0 = blockIdx.x * 256; m0 = blockIdx.y * 128; }

    const int NCH = (stage == 2) ? 8 : 32;

    const __nv_bfloat16 *Ah, *Al, *Bh, *Bl;
    long long aBase, bBase;
    int Astr, Bstr;
    if (stage == 0) {
        Ah = g_x_hi;  Al = g_x_lo;  Bh = g_wqk_hi; Bl = g_wqk_lo;
        aBase = (long long)m0 * DD; bBase = (long long)n0 * DD; Astr = DD; Bstr = DD;
    } else if (stage == 1) {
        Ah = g_q_hi;  Al = g_q_lo;  Bh = g_k_hi;   Bl = g_k_lo;
        aBase = ((long long)b * NN + (long long)w * WW) * DD;
        bBase = ((long long)b * NN + (long long)(w - 1) * WW) * DD;
        Astr = DD; Bstr = DD;
    } else if (stage == 2) {
        Ah = g_attn_hi; Al = g_attn_lo; Bh = g_kT_hi; Bl = g_kT_lo;
        aBase = ((long long)(b * NWIN + w) * WW) * 256;
        bBase = ((long long)(b * DD + n0)) * NN + (long long)(w - 1) * WW;
        Astr = 256; Bstr = NN;
    } else {
        Ah = g_ao_hi; Al = g_ao_lo; Bh = g_wo_hi; Bl = g_wo_lo;
        aBase = (long long)m0 * DD; bBase = (long long)n0 * DD; Astr = DD; Bstr = DD;
    }

    // init barriers: full/empty per buffer slot, count = all 512 threads
    if (t == 0) {
        #pragma unroll
        for (int s = 0; s < 3; s++) {
            MBAR_INIT(mbF + s * 8, NT);
            MBAR_INIT(mbE + s * 8, NT);
        }
    }
    __syncthreads();

    // ldmatrix lane addresses (buffer 0, k16 step 0; add per-chunk offsets)
    uint32_t aAddr[2], bAddr[4];
    {
        const int rowA = lane & 15;
        const int khA  = (lane >> 4) * 16;
        #pragma unroll
        for (int fm = 0; fm < 2; fm++)
            aAddr[fm] = smb + A_HI + (uint32_t)((wm * 32 + fm * 16 + rowA) * RS + khA);
        const int rowB = (lane & 7) + ((lane >> 4) & 1) * 8;
        const int khB  = ((lane >> 3) & 1) * 16;
        #pragma unroll
        for (int p = 0; p < 4; p++)
            bAddr[p] = smb + B_HI + (uint32_t)((wn * 64 + p * 16 + rowB) * RS + khB);
    }

    float acc[2][8][4];
    #pragma unroll
    for (int i = 0; i < 2; i++)
        #pragma unroll
        for (int j = 0; j < 8; j++)
            #pragma unroll
            for (int e = 0; e < 4; e++) acc[i][j][e] = 0.f;

    // prologue: fill all 3 slots (NCH >= 8 for every stage)
    #pragma unroll
    for (int cc = 0; cc < 3; cc++) {
        load_chunk_async(smb, cc, cc, stage, w, t,
                         Ah, Al, Bh, Bl, aBase, bBase, Astr, Bstr);
        CPA_MBAR_ARRIVE(mbF + cc * 8);
    }

    // main loop: slot s = c % 3, parity p = (c/3) & 1 (tracked incrementally)
    int s = 0, p = 0;
    #pragma unroll 1
    for (int c = 0; c < NCH; c++) {
        MBAR_WAIT(mbF + s * 8, p);               // chunk c resident (all threads)
        compute_chunk((uint32_t)(s * BUFB), aAddr, bAddr, acc);
        MBAR_ARRIVE(mbE + s * 8);                // release buffer s
        const int cc = c + 3;
        if (cc < NCH) {
            MBAR_WAIT(mbE + s * 8, p);           // all 512 released slot s
            load_chunk_async(smb, cc, s, stage, w, t,
                             Ah, Al, Bh, Bl, aBase, bBase, Astr, Bstr);
            CPA_MBAR_ARRIVE(mbF + s * 8);
        }
        if (++s == 3) { s = 0; p ^= 1; }
    }
    __syncthreads();

    // ---- stage D[128,256] into smem [128][257] fp32 (aliases buffers) ----
    float* stg = (float*)sm;
    #pragma unroll
    for (int fm = 0; fm < 2; fm++) {
        const int r0 = wm * 32 + fm * 16 + g;
        #pragma unroll
        for (int fn = 0; fn < 8; fn++) {
            const int c0 = wn * 64 + fn * 8 + tg * 2;
            stg[r0 * 257 + c0]           = acc[fm][fn][0];
            stg[r0 * 257 + c0 + 1]       = acc[fm][fn][1];
            stg[(r0 + 8) * 257 + c0]     = acc[fm][fn][2];
            stg[(r0 + 8) * 257 + c0 + 1] = acc[fm][fn][3];
        }
    }
    __syncthreads();

    // ---- stage-specific epilogue (512 threads: col = t&255, 2 row-slices) --
    const int wg = wid;
    const int col = t & 255;
    const int rb  = t >> 8;            // 0 or 1
    if (stage == 0) {
        const bool isQ = (n0 < 1024);
        __nv_bfloat16* dh = isQ ? g_q_hi : g_k_hi;
        __nv_bfloat16* dl = isQ ? g_q_lo : g_k_lo;
        const int nq = isQ ? n0 : (n0 - 1024);
        #pragma unroll 4
        for (int rr = 0; rr < 64; rr++) {
            const int r = rb + rr * 2;
            float v = stg[r * 257 + col];
            __nv_bfloat16 hi, lo; f2bf_split(v, hi, lo);
            size_t o = (size_t)(m0 + r) * DD + nq + col;
            dh[o] = hi; dl[o] = lo;
        }
    } else if (stage == 1) {
        const int rowbase = (b * NWIN + w) * WW;
        for (int rr = 0; rr < 8; rr++) {
            const int r = wg * 8 + rr;
            float vv[8];
            float mx = -FLT_MAX;
            #pragma unroll
            for (int u = 0; u < 8; u++) {
                int j = lane + u * 32;
                float sc = stg[r * 257 + j] * 0.03125f;
                vv[u] = (j <= r + 128) ? sc : -FLT_MAX;
                mx = fmaxf(mx, vv[u]);
            }
            #pragma unroll
            for (int off = 16; off; off >>= 1)
                mx = fmaxf(mx, __shfl_xor_sync(0xffffffffu, mx, off));
            float sum = 0.f;
            #pragma unroll
            for (int u = 0; u < 8; u++) {
                int j = lane + u * 32;
                float e = (j <= r + 128) ? expf(vv[u] - mx) : 0.f;
                sum += e;
                __nv_bfloat16 hi, lo; f2bf_split(e, hi, lo);
                size_t o = (size_t)(rowbase + r) * 256 + j;
                g_attn_hi[o] = hi; g_attn_lo[o] = lo;
            }
            #pragma unroll
            for (int off = 16; off; off >>= 1)
                sum += __shfl_xor_sync(0xffffffffu, sum, off);
            if (lane == 0) g_invsum[rowbase + r] = 1.f / sum;
        }
    } else if (stage == 2) {
        const int rowbase = (b * NWIN + w) * WW;
        #pragma unroll 4
        for (int rr = 0; rr < 64; rr++) {
            const int r = rb + rr * 2;
            float v = stg[r * 257 + col] * g_invsum[rowbase + r];
            __nv_bfloat16 hi, lo; f2bf_split(v, hi, lo);
            size_t o = ((size_t)b * NN + (size_t)w * WW + r) * DD + n0 + col;
            g_ao_hi[o] = hi; g_ao_lo[o] = lo;
        }
    } else {
        const float bv = bias[n0 + col];
        #pragma unroll 4
        for (int rr = 0; rr < 64; rr++) {
            const int r = rb + rr * 2;
            dOut[(size_t)(m0 + r) * DD + n0 + col] = stg[r * 257 + col] + bv;
        }
    }
}

// ---------------------------------------------------------------------------
// Converters — destinations are device globals referenced IN DEVICE CODE ONLY
// ---------------------------------------------------------------------------
__global__ void convert_x_kernel(const float* __restrict__ x)
{
    size_t i = ((size_t)blockIdx.x * blockDim.x + threadIdx.x) * 4;
    float4 v = *(const float4*)(x + i);
    float vals[4] = { v.x, v.y, v.z, v.w };
    #pragma unroll
    for (int j = 0; j < 4; j++) {
        __nv_bfloat16 hi, lo; f2bf_split(vals[j], hi, lo);
        g_x_hi[i + j] = hi;
        g_x_lo[i + j] = lo;
    }
}

// dst[n][k] = src[k][n], bf16 hi/lo split; which: 0 -> wqk, 1 -> wo.
__global__ void transpose_convert_w(const float* __restrict__ src, int ld, int which)
{
    __nv_bfloat16* dh = (which == 0) ? g_wqk_hi : g_wo_hi;
    __nv_bfloat16* dl = (which == 0) ? g_wqk_lo : g_wo_lo;
    __shared__ float sh[32][33];
    const int n0 = blockIdx.x * 32, k0 = blockIdx.y * 32;
    const int tx = threadIdx.x, ty = threadIdx.y;
    #pragma unroll
    for (int i = 0; i < 4; i++)
        sh[ty + 8 * i][tx] = src[(size_t)(k0 + ty + 8 * i) * ld + n0 + tx];
    __syncthreads();
    #pragma unroll
    for (int i = 0; i < 4; i++) {
        float v = sh[tx][ty + 8 * i];
        int n = n0 + ty + 8 * i, k = k0 + tx;
        __nv_bfloat16 hi, lo; f2bf_split(v, hi, lo);
        dh[(size_t)n * DD + k] = hi;
        dl[(size_t)n * DD + k] = lo;
    }
}

// kT[b][d][t] = k[b][t][d]. grid: (1024/32, 4096/32, 4), block (32,8)
__global__ void transpose_k_kernel()
{
    __shared__ __nv_bfloat16 shh[32][34];
    __shared__ __nv_bfloat16 shl[32][34];
    const int d0 = blockIdx.x * 32, t0 = blockIdx.y * 32, b = blockIdx.z;
    const int tx = threadIdx.x, ty = threadIdx.y;
    #pragma unroll
    for (int i = 0; i < 4; i++) {
        int tok = t0 + ty + 8 * i;
        size_t o = ((size_t)b * NN + tok) * DD + d0 + tx;
        shh[ty + 8 * i][tx] = g_k_hi[o];
        shl[ty + 8 * i][tx] = g_k_lo[o];
    }
    __syncthreads();
    #pragma unroll
    for (int i = 0; i < 4; i++) {
        int d = d0 + ty + 8 * i;
        size_t o = ((size_t)b * DD + d) * NN + t0 + tx;
        g_kT_hi[o] = shh[tx][ty + 8 * i];
        g_kT_lo[o] = shl[tx][ty + 8 * i];
    }
}

// ---------------------------------------------------------------------------
extern "C" void kernel_launch(void* const* d_in, const int* in_sizes, int n_in,
                              void* d_out, int out_size)
{
    (void)in_sizes; (void)n_in; (void)out_size;
    const float* x     = (const float*)d_in[0];   // [4,4096,1024]
    const float* w_qkv = (const float*)d_in[1];   // [1024,3072]
    const float* w_out = (const float*)d_in[2];   // [1024,1024]
    const float* b_out = (const float*)d_in[3];   // [1024]
    float* out = (float*)d_out;                   // [4,4096,1024]

    cudaFuncSetAttribute(mma_gemm, cudaFuncAttributeMaxDynamicSharedMemorySize, SMEMB);

    // 1) split inputs into bf16 hi/lo
    convert_x_kernel<<<MTOT * DD / 1024, 256>>>(x);
    transpose_convert_w<<<dim3(64, 32), dim3(32, 8)>>>(w_qkv, 3072, 0);
    transpose_convert_w<<<dim3(32, 32), dim3(32, 8)>>>(w_out, 1024, 1);

    // 2) qk = x @ w_qkv[:, :2048]   (mma.sync bf16x3, mbarrier pipeline)
    mma_gemm<<<dim3(8, 128), NT, SMEMB>>>(0, nullptr, nullptr);

    // 3) k transposed per batch for the attn*V GEMM
    transpose_k_kernel<<<dim3(32, 128, 4), dim3(32, 8)>>>();

    // 4) sim = q @ k2^T, softmax fused (unnormalized exp + invsum)
    mma_gemm<<<dim3(NWIN, BB), NT, SMEMB>>>(1, nullptr, nullptr);

    // 5) ao = attn @ k2 (values == keys per reference bug)
    mma_gemm<<<dim3(4, NWIN, BB), NT, SMEMB>>>(2, nullptr, nullptr);

    // 6) out = ao @ w_out + b_out
    mma_gemm<<<dim3(4, 128), NT, SMEMB>>>(3, out, b_out);
}

// round 14
// speedup vs baseline: 1.0734x; 1.0734x over previous
#include <cuda_runtime.h>
#include <cuda_bf16.h>
#include <cstdint>
#include <math.h>
#include <float.h>

#define BB   4
#define NN   4096
#define DD   1024
#define WW   128
#define NWIN (NN / WW)          // 32
#define MTOT (BB * NN)          // 16384

// ---------------------------------------------------------------------------
// bf16 hi/lo split scratch. ONLY referenced from device code — NEVER passed
// as kernel args from host (host-side &symbol is the shadow copy; GB300 ATS
// makes writes to it silently land in host memory).
// ---------------------------------------------------------------------------
__device__ __nv_bfloat16 g_x_hi  [(size_t)MTOT * DD];
__device__ __nv_bfloat16 g_x_lo  [(size_t)MTOT * DD];
__device__ __nv_bfloat16 g_wqk_hi[(size_t)2048 * DD];   // [n][k] = w_qkv[k][n]
__device__ __nv_bfloat16 g_wqk_lo[(size_t)2048 * DD];
__device__ __nv_bfloat16 g_wo_hi [(size_t)1024 * DD];   // [n][k] = w_out[k][n]
__device__ __nv_bfloat16 g_wo_lo [(size_t)1024 * DD];
__device__ __nv_bfloat16 g_q_hi  [(size_t)MTOT * DD];
__device__ __nv_bfloat16 g_q_lo  [(size_t)MTOT * DD];
__device__ __nv_bfloat16 g_k_hi  [(size_t)MTOT * DD];
__device__ __nv_bfloat16 g_k_lo  [(size_t)MTOT * DD];
__device__ __nv_bfloat16 g_ao_hi [(size_t)MTOT * DD];
__device__ __nv_bfloat16 g_ao_lo [(size_t)MTOT * DD];
// zero source for masked cp.async (device globals are zero-initialized)
__device__ __align__(16) __nv_bfloat16 g_zero[16];

// ---------------------------------------------------------------------------
// primitives
// ---------------------------------------------------------------------------
__device__ __forceinline__ uint32_t smem_u32(const void* p) {
    uint32_t a;
    asm("{ .reg .u64 t; cvta.to.shared.u64 t, %1; cvt.u32.u64 %0, t; }"
        : "=r"(a) : "l"(p));
    return a;
}

__device__ __forceinline__ void mma16816(float* c, const uint32_t* a, const uint32_t* b) {
    asm volatile(
        "mma.sync.aligned.m16n8k16.row.col.f32.bf16.bf16.f32 "
        "{%0,%1,%2,%3}, {%4,%5,%6,%7}, {%8,%9}, {%0,%1,%2,%3};"
        : "+f"(c[0]), "+f"(c[1]), "+f"(c[2]), "+f"(c[3])
        : "r"(a[0]), "r"(a[1]), "r"(a[2]), "r"(a[3]), "r"(b[0]), "r"(b[1]));
}

__device__ __forceinline__ void ldsm_x4(uint32_t& d0, uint32_t& d1,
                                        uint32_t& d2, uint32_t& d3, uint32_t a) {
    asm volatile("ldmatrix.sync.aligned.m8n8.x4.shared.b16 {%0,%1,%2,%3}, [%4];"
                 : "=r"(d0), "=r"(d1), "=r"(d2), "=r"(d3) : "r"(a));
}

__device__ __forceinline__ void ldsm_x4_trans(uint32_t& d0, uint32_t& d1,
                                              uint32_t& d2, uint32_t& d3, uint32_t a) {
    asm volatile("ldmatrix.sync.aligned.m8n8.x4.trans.shared.b16 {%0,%1,%2,%3}, [%4];"
                 : "=r"(d0), "=r"(d1), "=r"(d2), "=r"(d3) : "r"(a));
}

__device__ __forceinline__ void cp16(uint32_t dst, const void* src) {
    asm volatile("cp.async.cg.shared.global [%0], [%1], 16;"
                 :: "r"(dst), "l"(src) : "memory");
}
#define CP_COMMIT() asm volatile("cp.async.commit_group;" ::: "memory")
#define CP_WAIT1()  asm volatile("cp.async.wait_group 1;" ::: "memory")
#define CP_WAIT0()  asm volatile("cp.async.wait_group 0;" ::: "memory")

__device__ __forceinline__ void f2bf_split(float v, __nv_bfloat16& hi, __nv_bfloat16& lo) {
    hi = __float2bfloat16(v);
    lo = __float2bfloat16(v - __bfloat162float(hi));
}

// GEMM smem per buffer: K-chunk 32 -> 64B data + 16B pad = 80B row stride.
#define RS    80
#define A_HI  0
#define A_LO  10240
#define B_HI  20480
#define B_LO  40960
#define BUFB  61440
#define SMEMB (3 * BUFB)        // 184320; stg 128*257*4=131584 aliases it
#define NT    512               // 16 warps: 4x4 warp grid, warp tile 32x64

// fused-attention smem map:
//   phase A ring: 3 x BUFB at [0, 184320)
//   stg/attn:     128 rows x 1040B at [0, 133120)  (aliases ring after drain)
//                 row = 260 fp32 during staging; then attn_hi[256]@+0,
//                 attn_lo[256]@+512 (bf16, in-place)
//   phase B ring: 2 slots x 33792B at [133120, 200704)
//                 slot: k2_hi [32 tok][528B] @ +0, k2_lo @ +16896
#define F_ATTN   133120
#define F_SLOT   33792
#define SMEMB_F  (F_ATTN + 2 * F_SLOT)   // 200704

// ---------------------------------------------------------------------------
// GEMM chunk loader (A[128]x32 + B[256]x32, hi+lo); stage1 masks zero-block
// ---------------------------------------------------------------------------
__device__ __forceinline__ void load_chunk_async(
    char* sm, uint32_t smb, int cc, int bufIdx, int stage, int w, int t,
    const __nv_bfloat16* Ah, const __nv_bfloat16* Al,
    const __nv_bfloat16* Bh, const __nv_bfloat16* Bl,
    long long aBase, long long bBase)
{
    const int kE = cc * 32;
    const uint32_t bo = (uint32_t)bufIdx * BUFB;
    const uint4 z = make_uint4(0u, 0u, 0u, 0u);
    {
        const int r = t >> 2, sg = t & 3;
        const long long off = aBase + (long long)r * DD + kE + sg * 8;
        const uint32_t d = smb + bo + A_HI + r * RS + sg * 16;
        cp16(d, Ah + off);
        cp16(d + (A_LO - A_HI), Al + off);
    }
    #pragma unroll
    for (int i = 0; i < 2; i++) {
        const int idx = t + i * NT;
        const int r = idx >> 2, sg = idx & 3;
        bool v = true;
        if (stage == 1) v = (w > 0) || (r >= 128);
        const int o = B_HI + r * RS + sg * 16;
        if (v) {
            const long long off = bBase + (long long)r * DD + kE + sg * 8;
            cp16(smb + bo + o, Bh + off);
            cp16(smb + bo + o + (B_LO - B_HI), Bl + off);
        } else {
            *(uint4*)(sm + bo + o) = z;
            *(uint4*)(sm + bo + o + (B_LO - B_HI)) = z;
        }
    }
}

// one K-chunk (k=32): bf16x3 (AhBh + AhBl + AlBh), warp tile 32x64
__device__ __forceinline__ void compute_chunk(
    uint32_t bufAdd, const uint32_t* aAddr, const uint32_t* bAddr,
    float (&acc)[2][8][4])
{
    #pragma unroll
    for (int kk = 0; kk < 2; kk++) {
        const uint32_t kb = bufAdd + (uint32_t)kk * 32u;
        uint32_t A[2][4], B0[8][2], B1[8][2];
        #pragma unroll
        for (int fm = 0; fm < 2; fm++)
            ldsm_x4(A[fm][0], A[fm][1], A[fm][2], A[fm][3], aAddr[fm] + kb);
        #pragma unroll
        for (int p = 0; p < 4; p++)
            ldsm_x4(B0[2*p][0], B0[2*p][1], B0[2*p+1][0], B0[2*p+1][1],
                    bAddr[p] + kb);
        #pragma unroll
        for (int fm = 0; fm < 2; fm++)
            #pragma unroll
            for (int fn = 0; fn < 8; fn++)
                mma16816(acc[fm][fn], A[fm], B0[fn]);    // Ah*Bh
        #pragma unroll
        for (int p = 0; p < 4; p++)
            ldsm_x4(B1[2*p][0], B1[2*p][1], B1[2*p+1][0], B1[2*p+1][1],
                    bAddr[p] + kb + (B_LO - B_HI));
        #pragma unroll
        for (int fm = 0; fm < 2; fm++)
            #pragma unroll
            for (int fn = 0; fn < 8; fn++)
                mma16816(acc[fm][fn], A[fm], B1[fn]);    // Ah*Bl
        #pragma unroll
        for (int fm = 0; fm < 2; fm++)
            ldsm_x4(A[fm][0], A[fm][1], A[fm][2], A[fm][3],
                    aAddr[fm] + kb + (A_LO - A_HI));
        #pragma unroll
        for (int fm = 0; fm < 2; fm++)
            #pragma unroll
            for (int fn = 0; fn < 8; fn++)
                mma16816(acc[fm][fn], A[fm], B0[fn]);    // Al*Bh
    }
}

// ---------------------------------------------------------------------------
// GEMM kernel (stages 0 and 3) — R10 engine verbatim
// stage 0: QKV  A=x  B=wqkT  -> g_q / g_k (hi/lo)
// stage 3: OUT  A=ao B=woT   -> d_out + bias (fp32)
// ---------------------------------------------------------------------------
__global__ void __launch_bounds__(NT, 1) mma_gemm(int stage,
                                                  float* __restrict__ dOut,
                                                  const float* __restrict__ bias)
{
    extern __shared__ char sm[];
    const uint32_t smb = smem_u32(sm);
    const int t = threadIdx.x;
    const int lane = t & 31, wid = t >> 5;
    const int wm = wid & 3, wn = wid >> 2;
    const int g = lane >> 2, tg = lane & 3;

    const int n0 = blockIdx.x * 256;
    const int m0 = blockIdx.y * 128;

    const __nv_bfloat16 *Ah, *Al, *Bh, *Bl;
    if (stage == 0) { Ah = g_x_hi;  Al = g_x_lo;  Bh = g_wqk_hi; Bl = g_wqk_lo; }
    else            { Ah = g_ao_hi; Al = g_ao_lo; Bh = g_wo_hi;  Bl = g_wo_lo; }
    const long long aBase = (long long)m0 * DD;
    const long long bBase = (long long)n0 * DD;

    uint32_t aAddr[2], bAddr[4];
    {
        const int rowA = lane & 15;
        const int khA  = (lane >> 4) * 16;
        #pragma unroll
        for (int fm = 0; fm < 2; fm++)
            aAddr[fm] = smb + A_HI + (uint32_t)((wm * 32 + fm * 16 + rowA) * RS + khA);
        const int rowB = (lane & 7) + ((lane >> 4) & 1) * 8;
        const int khB  = ((lane >> 3) & 1) * 16;
        #pragma unroll
        for (int p = 0; p < 4; p++)
            bAddr[p] = smb + B_HI + (uint32_t)((wn * 64 + p * 16 + rowB) * RS + khB);
    }

    float acc[2][8][4];
    #pragma unroll
    for (int i = 0; i < 2; i++)
        #pragma unroll
        for (int j = 0; j < 8; j++)
            #pragma unroll
            for (int e = 0; e < 4; e++) acc[i][j][e] = 0.f;

    const int NCH = 32;
    load_chunk_async(sm, smb, 0, 0, stage, 0, t, Ah, Al, Bh, Bl, aBase, bBase);
    CP_COMMIT();
    load_chunk_async(sm, smb, 1, 1, stage, 0, t, Ah, Al, Bh, Bl, aBase, bBase);
    CP_COMMIT();

    #pragma unroll 1
    for (int c = 0; c < NCH; c++) {
        CP_WAIT1();
        __syncthreads();
        compute_chunk((uint32_t)((c % 3) * BUFB), aAddr, bAddr, acc);
        const int cc = c + 2;
        if (cc < NCH)
            load_chunk_async(sm, smb, cc, cc % 3, stage, 0, t,
                             Ah, Al, Bh, Bl, aBase, bBase);
        CP_COMMIT();
    }
    __syncthreads();

    float* stg = (float*)sm;
    #pragma unroll
    for (int fm = 0; fm < 2; fm++) {
        const int r0 = wm * 32 + fm * 16 + g;
        #pragma unroll
        for (int fn = 0; fn < 8; fn++) {
            const int c0 = wn * 64 + fn * 8 + tg * 2;
            stg[r0 * 257 + c0]           = acc[fm][fn][0];
            stg[r0 * 257 + c0 + 1]       = acc[fm][fn][1];
            stg[(r0 + 8) * 257 + c0]     = acc[fm][fn][2];
            stg[(r0 + 8) * 257 + c0 + 1] = acc[fm][fn][3];
        }
    }
    __syncthreads();

    const int col = t & 255;
    const int rb  = t >> 8;
    if (stage == 0) {
        const bool isQ = (n0 < 1024);
        __nv_bfloat16* dh = isQ ? g_q_hi : g_k_hi;
        __nv_bfloat16* dl = isQ ? g_q_lo : g_k_lo;
        const int nq = isQ ? n0 : (n0 - 1024);
        #pragma unroll 4
        for (int rr = 0; rr < 64; rr++) {
            const int r = rb + rr * 2;
            float v = stg[r * 257 + col];
            __nv_bfloat16 hi, lo; f2bf_split(v, hi, lo);
            size_t o = (size_t)(m0 + r) * DD + nq + col;
            dh[o] = hi; dl[o] = lo;
        }
    } else {
        const float bv = bias[n0 + col];
        #pragma unroll 4
        for (int rr = 0; rr < 64; rr++) {
            const int r = rb + rr * 2;
            dOut[(size_t)(m0 + r) * DD + n0 + col] = stg[r * 257 + col] + bv;
        }
    }
}

// ---------------------------------------------------------------------------
// Fused attention kernel: one CTA per (w, b).
// Phase A: sim = q @ k2^T (K=1024, R10 engine), softmax -> attn (smem, bf16x2)
// Phase B: ao = attn @ k2 via ldmatrix.trans on [token][dim] k2 tiles (K=256)
// ---------------------------------------------------------------------------
__device__ __forceinline__ void load_pv_chunk(
    uint32_t smb, int b, int w, int n0, int cc, int slot, int t)
{
    const uint32_t sb = smb + F_ATTN + (uint32_t)slot * F_SLOT;
    #pragma unroll
    for (int i = 0; i < 2; i++) {
        const int idx = t + i * NT;           // 0..1023
        const int r = idx >> 5, sg = idx & 31;
        const int tokLocal = cc * 32 + r;     // 0..255 within the 2-window span
        const bool v = (w > 0) || (tokLocal >= 128);
        const long long off =
            ((long long)b * NN + (long long)(w - 1) * WW + tokLocal) * DD + n0 + sg * 8;
        const __nv_bfloat16* sh = v ? (g_k_hi + off) : g_zero;
        const __nv_bfloat16* sl = v ? (g_k_lo + off) : g_zero;
        const uint32_t d = sb + (uint32_t)(r * 528 + sg * 16);
        cp16(d, sh);
        cp16(d + 16896, sl);
    }
}

__device__ __forceinline__ void compute_pv(
    uint32_t slotOff, uint32_t aOffC, const uint32_t* aA, const uint32_t* bT,
    float (&acc)[2][8][4])
{
    #pragma unroll
    for (int kk = 0; kk < 2; kk++) {
        const uint32_t ao = aOffC + (uint32_t)kk * 32u;        // attn col bytes
        const uint32_t bo = slotOff + (uint32_t)kk * 8448u;    // 16 rows * 528
        uint32_t A[2][4], B0[8][2], B1[8][2];
        #pragma unroll
        for (int fm = 0; fm < 2; fm++)
            ldsm_x4(A[fm][0], A[fm][1], A[fm][2], A[fm][3], aA[fm] + ao);
        #pragma unroll
        for (int p = 0; p < 4; p++)
            ldsm_x4_trans(B0[2*p][0], B0[2*p][1], B0[2*p+1][0], B0[2*p+1][1],
                          bT[p] + bo);
        #pragma unroll
        for (int fm = 0; fm < 2; fm++)
            #pragma unroll
            for (int fn = 0; fn < 8; fn++)
                mma16816(acc[fm][fn], A[fm], B0[fn]);    // Ah*Bh
        #pragma unroll
        for (int p = 0; p < 4; p++)
            ldsm_x4_trans(B1[2*p][0], B1[2*p][1], B1[2*p+1][0], B1[2*p+1][1],
                          bT[p] + bo + 16896u);
        #pragma unroll
        for (int fm = 0; fm < 2; fm++)
            #pragma unroll
            for (int fn = 0; fn < 8; fn++)
                mma16816(acc[fm][fn], A[fm], B1[fn]);    // Ah*Bl
        #pragma unroll
        for (int fm = 0; fm < 2; fm++)
            ldsm_x4(A[fm][0], A[fm][1], A[fm][2], A[fm][3],
                    aA[fm] + ao + 512u);
        #pragma unroll
        for (int fm = 0; fm < 2; fm++)
            #pragma unroll
            for (int fn = 0; fn < 8; fn++)
                mma16816(acc[fm][fn], A[fm], B0[fn]);    // Al*Bh
    }
}

__global__ void __launch_bounds__(NT, 1) fused_attn()
{
    extern __shared__ char sm[];
    const uint32_t smb = smem_u32(sm);
    const int t = threadIdx.x;
    const int lane = t & 31, wid = t >> 5;
    const int wm = wid & 3, wn = wid >> 2;
    const int g = lane >> 2, tg = lane & 3;
    const int w = blockIdx.x, b = blockIdx.y;

    // ---- Phase A: sim = q @ k2^T (identical engine to stage 1) ----
    const long long aBase = ((long long)b * NN + (long long)w * WW) * DD;
    const long long bBase = ((long long)b * NN + (long long)(w - 1) * WW) * DD;

    uint32_t aAddr[2], bAddr[4];
    {
        const int rowA = lane & 15;
        const int khA  = (lane >> 4) * 16;
        #pragma unroll
        for (int fm = 0; fm < 2; fm++)
            aAddr[fm] = smb + A_HI + (uint32_t)((wm * 32 + fm * 16 + rowA) * RS + khA);
        const int rowB = (lane & 7) + ((lane >> 4) & 1) * 8;
        const int khB  = ((lane >> 3) & 1) * 16;
        #pragma unroll
        for (int p = 0; p < 4; p++)
            bAddr[p] = smb + B_HI + (uint32_t)((wn * 64 + p * 16 + rowB) * RS + khB);
    }

    float acc[2][8][4];
    #pragma unroll
    for (int i = 0; i < 2; i++)
        #pragma unroll
        for (int j = 0; j < 8; j++)
            #pragma unroll
            for (int e = 0; e < 4; e++) acc[i][j][e] = 0.f;

    load_chunk_async(sm, smb, 0, 0, 1, w, t, g_q_hi, g_q_lo, g_k_hi, g_k_lo, aBase, bBase);
    CP_COMMIT();
    load_chunk_async(sm, smb, 1, 1, 1, w, t, g_q_hi, g_q_lo, g_k_hi, g_k_lo, aBase, bBase);
    CP_COMMIT();

    #pragma unroll 1
    for (int c = 0; c < 32; c++) {
        CP_WAIT1();
        __syncthreads();
        compute_chunk((uint32_t)((c % 3) * BUFB), aAddr, bAddr, acc);
        const int cc = c + 2;
        if (cc < 32)
            load_chunk_async(sm, smb, cc, cc % 3, 1, w, t,
                             g_q_hi, g_q_lo, g_k_hi, g_k_lo, aBase, bBase);
        CP_COMMIT();
    }
    __syncthreads();

    // ---- stage acc -> stg [128][260] fp32 (row stride 1040B) ----
    float* stg = (float*)sm;
    #pragma unroll
    for (int fm = 0; fm < 2; fm++) {
        const int r0 = wm * 32 + fm * 16 + g;
        #pragma unroll
        for (int fn = 0; fn < 8; fn++) {
            const int c0 = wn * 64 + fn * 8 + tg * 2;
            stg[r0 * 260 + c0]           = acc[fm][fn][0];
            stg[r0 * 260 + c0 + 1]       = acc[fm][fn][1];
            stg[(r0 + 8) * 260 + c0]     = acc[fm][fn][2];
            stg[(r0 + 8) * 260 + c0 + 1] = acc[fm][fn][3];
        }
    }
    __syncthreads();

    // ---- softmax, normalized, in-place -> attn_hi @ row+0, attn_lo @ row+512
    for (int rr = 0; rr < 8; rr++) {
        const int r = wid * 8 + rr;
        float vv[8];
        float mx = -FLT_MAX;
        #pragma unroll
        for (int u = 0; u < 8; u++) {
            int j = lane + u * 32;
            float sc = stg[r * 260 + j] * 0.03125f;
            vv[u] = (j <= r + 128) ? sc : -FLT_MAX;
            mx = fmaxf(mx, vv[u]);
        }
        #pragma unroll
        for (int off = 16; off; off >>= 1)
            mx = fmaxf(mx, __shfl_xor_sync(0xffffffffu, mx, off));
        float sum = 0.f;
        #pragma unroll
        for (int u = 0; u < 8; u++) {
            int j = lane + u * 32;
            vv[u] = (j <= r + 128) ? expf(vv[u] - mx) : 0.f;
            sum += vv[u];
        }
        #pragma unroll
        for (int off = 16; off; off >>= 1)
            sum += __shfl_xor_sync(0xffffffffu, sum, off);
        const float inv = 1.f / sum;
        __nv_bfloat16* arow = (__nv_bfloat16*)(sm + (size_t)r * 1040);
        #pragma unroll
        for (int u = 0; u < 8; u++) {
            int j = lane + u * 32;
            __nv_bfloat16 hi, lo; f2bf_split(vv[u] * inv, hi, lo);
            arow[j]       = hi;
            arow[256 + j] = lo;     // +512 bytes
        }
    }
    __syncthreads();

    // ---- Phase B: ao = attn @ k2, 4 N-iterations of 256 dims ----
    uint32_t aA[2], bT[4];
    {
        const int rowA = lane & 15;
        #pragma unroll
        for (int fm = 0; fm < 2; fm++)
            aA[fm] = smb + (uint32_t)((wm * 32 + fm * 16 + rowA) * 1040
                                      + ((lane >> 4) & 1) * 16);
        const int rowK = (lane & 7) + ((lane >> 3) & 1) * 8;   // k row 0..15
        const int dsel = ((lane >> 4) & 1) * 8;                // dim seg
        #pragma unroll
        for (int p = 0; p < 4; p++)
            bT[p] = smb + F_ATTN + (uint32_t)(rowK * 528
                                              + (wn * 64 + p * 16 + dsel) * 2);
    }

    #pragma unroll 1
    for (int niter = 0; niter < 4; niter++) {
        const int n0 = niter * 256;
        float acc2[2][8][4];
        #pragma unroll
        for (int i = 0; i < 2; i++)
            #pragma unroll
            for (int j = 0; j < 8; j++)
                #pragma unroll
                for (int e = 0; e < 4; e++) acc2[i][j][e] = 0.f;

        load_pv_chunk(smb, b, w, n0, 0, 0, t);
        CP_COMMIT();
        #pragma unroll 1
        for (int c = 0; c < 8; c++) {
            CP_WAIT0();
            __syncthreads();
            if (c < 7) {
                load_pv_chunk(smb, b, w, n0, c + 1, (c + 1) & 1, t);
                CP_COMMIT();
            }
            compute_pv((uint32_t)((c & 1) * F_SLOT), (uint32_t)(c * 64),
                       aA, bT, acc2);
        }

        // epilogue: split-store directly to g_ao (bf16x2 per 4B store)
        #pragma unroll
        for (int fm = 0; fm < 2; fm++) {
            const int r0 = wm * 32 + fm * 16 + g;
            #pragma unroll
            for (int fn = 0; fn < 8; fn++) {
                const int c0 = n0 + wn * 64 + fn * 8 + tg * 2;
                #pragma unroll
                for (int half = 0; half < 2; half++) {
                    const int r = r0 + half * 8;
                    const float v0 = acc2[fm][fn][half * 2];
                    const float v1 = acc2[fm][fn][half * 2 + 1];
                    __nv_bfloat16 h0, l0, h1, l1;
                    f2bf_split(v0, h0, l0);
                    f2bf_split(v1, h1, l1);
                    const size_t o = ((size_t)b * NN + (size_t)w * WW + r) * DD + c0;
                    __nv_bfloat162 hp; hp.x = h0; hp.y = h1;
                    __nv_bfloat162 lp; lp.x = l0; lp.y = l1;
                    *(__nv_bfloat162*)(g_ao_hi + o) = hp;
                    *(__nv_bfloat162*)(g_ao_lo + o) = lp;
                }
            }
        }
        // slot 0's last reader was chunk 6, synced at c=7; safe to reload next iter
    }
}

// ---------------------------------------------------------------------------
// Converters — destinations are device globals referenced IN DEVICE CODE ONLY
// ---------------------------------------------------------------------------
__global__ void convert_x_kernel(const float* __restrict__ x)
{
    size_t i = ((size_t)blockIdx.x * blockDim.x + threadIdx.x) * 4;
    float4 v = *(const float4*)(x + i);
    float vals[4] = { v.x, v.y, v.z, v.w };
    #pragma unroll
    for (int j = 0; j < 4; j++) {
        __nv_bfloat16 hi, lo; f2bf_split(vals[j], hi, lo);
        g_x_hi[i + j] = hi;
        g_x_lo[i + j] = lo;
    }
}

// dst[n][k] = src[k][n], bf16 hi/lo split; which: 0 -> wqk, 1 -> wo.
__global__ void transpose_convert_w(const float* __restrict__ src, int ld, int which)
{
    __nv_bfloat16* dh = (which == 0) ? g_wqk_hi : g_wo_hi;
    __nv_bfloat16* dl = (which == 0) ? g_wqk_lo : g_wo_lo;
    __shared__ float sh[32][33];
    const int n0 = blockIdx.x * 32, k0 = blockIdx.y * 32;
    const int tx = threadIdx.x, ty = threadIdx.y;
    #pragma unroll
    for (int i = 0; i < 4; i++)
        sh[ty + 8 * i][tx] = src[(size_t)(k0 + ty + 8 * i) * ld + n0 + tx];
    __syncthreads();
    #pragma unroll
    for (int i = 0; i < 4; i++) {
        float v = sh[tx][ty + 8 * i];
        int n = n0 + ty + 8 * i, k = k0 + tx;
        __nv_bfloat16 hi, lo; f2bf_split(v, hi, lo);
        dh[(size_t)n * DD + k] = hi;
        dl[(size_t)n * DD + k] = lo;
    }
}

// ---------------------------------------------------------------------------
extern "C" void kernel_launch(void* const* d_in, const int* in_sizes, int n_in,
                              void* d_out, int out_size)
{
    (void)in_sizes; (void)n_in; (void)out_size;
    const float* x     = (const float*)d_in[0];   // [4,4096,1024]
    const float* w_qkv = (const float*)d_in[1];   // [1024,3072]
    const float* w_out = (const float*)d_in[2];   // [1024,1024]
    const float* b_out = (const float*)d_in[3];   // [1024]
    float* out = (float*)d_out;                   // [4,4096,1024]

    cudaFuncSetAttribute(mma_gemm,   cudaFuncAttributeMaxDynamicSharedMemorySize, SMEMB);
    cudaFuncSetAttribute(fused_attn, cudaFuncAttributeMaxDynamicSharedMemorySize, SMEMB_F);

    // 1) split inputs into bf16 hi/lo
    convert_x_kernel<<<MTOT * DD / 1024, 256>>>(x);
    transpose_convert_w<<<dim3(64, 32), dim3(32, 8)>>>(w_qkv, 3072, 0);
    transpose_convert_w<<<dim3(32, 32), dim3(32, 8)>>>(w_out, 1024, 1);

    // 2) qk = x @ w_qkv[:, :2048]   (mma.sync bf16x3)
    mma_gemm<<<dim3(8, 128), NT, SMEMB>>>(0, nullptr, nullptr);

    // 3) fused: sim = q@k2^T, softmax, ao = attn@k2 (values==keys ref bug)
    fused_attn<<<dim3(NWIN, BB), NT, SMEMB_F>>>();

    // 4) out = ao @ w_out + b_out
    mma_gemm<<<dim3(4, 128), NT, SMEMB>>>(3, out, b_out);
}

// round 15
// speedup vs baseline: 1.4427x; 1.3441x over previous
#include <cuda_runtime.h>
#include <cuda_bf16.h>
#include <cuda_fp16.h>
#include <cstdint>
#include <math.h>
#include <float.h>

#define BB   4
#define NN   4096
#define DD   1024
#define WW   128
#define NWIN (NN / WW)          // 32
#define MTOT (BB * NN)          // 16384

// ---------------------------------------------------------------------------
// Scratch. ONLY referenced from device code — NEVER passed as kernel args from
// host (host-side &symbol is the shadow copy; GB300 ATS silently swallows it).
// fp16 hi/lo feeds the big GEMMs (2-product split); bf16 hi/lo feeds the
// fused attention (3-product split, higher accuracy where error compounds).
// ---------------------------------------------------------------------------
__device__ __half g_x16_hi [(size_t)MTOT * DD];
__device__ __half g_x16_lo [(size_t)MTOT * DD];
__device__ __half g_w16qk  [(size_t)2048 * DD];   // [n][k] = w_qkv[k][n], hi only
__device__ __half g_w16o   [(size_t)1024 * DD];   // [n][k] = w_out[k][n], hi only
__device__ __half g_ao16_hi[(size_t)MTOT * DD];
__device__ __half g_ao16_lo[(size_t)MTOT * DD];
__device__ __nv_bfloat16 g_q_hi[(size_t)MTOT * DD];
__device__ __nv_bfloat16 g_q_lo[(size_t)MTOT * DD];
__device__ __nv_bfloat16 g_k_hi[(size_t)MTOT * DD];
__device__ __nv_bfloat16 g_k_lo[(size_t)MTOT * DD];
__device__ __align__(16) __nv_bfloat16 g_zero[16];  // zero-init BSS

// ---------------------------------------------------------------------------
// primitives
// ---------------------------------------------------------------------------
__device__ __forceinline__ uint32_t smem_u32(const void* p) {
    uint32_t a;
    asm("{ .reg .u64 t; cvta.to.shared.u64 t, %1; cvt.u32.u64 %0, t; }"
        : "=r"(a) : "l"(p));
    return a;
}

__device__ __forceinline__ void mma_bf16(float* c, const uint32_t* a, const uint32_t* b) {
    asm volatile(
        "mma.sync.aligned.m16n8k16.row.col.f32.bf16.bf16.f32 "
        "{%0,%1,%2,%3}, {%4,%5,%6,%7}, {%8,%9}, {%0,%1,%2,%3};"
        : "+f"(c[0]), "+f"(c[1]), "+f"(c[2]), "+f"(c[3])
        : "r"(a[0]), "r"(a[1]), "r"(a[2]), "r"(a[3]), "r"(b[0]), "r"(b[1]));
}

__device__ __forceinline__ void mma_fp16(float* c, const uint32_t* a, const uint32_t* b) {
    asm volatile(
        "mma.sync.aligned.m16n8k16.row.col.f32.f16.f16.f32 "
        "{%0,%1,%2,%3}, {%4,%5,%6,%7}, {%8,%9}, {%0,%1,%2,%3};"
        : "+f"(c[0]), "+f"(c[1]), "+f"(c[2]), "+f"(c[3])
        : "r"(a[0]), "r"(a[1]), "r"(a[2]), "r"(a[3]), "r"(b[0]), "r"(b[1]));
}

__device__ __forceinline__ void ldsm_x4(uint32_t& d0, uint32_t& d1,
                                        uint32_t& d2, uint32_t& d3, uint32_t a) {
    asm volatile("ldmatrix.sync.aligned.m8n8.x4.shared.b16 {%0,%1,%2,%3}, [%4];"
                 : "=r"(d0), "=r"(d1), "=r"(d2), "=r"(d3) : "r"(a));
}

__device__ __forceinline__ void ldsm_x4_trans(uint32_t& d0, uint32_t& d1,
                                              uint32_t& d2, uint32_t& d3, uint32_t a) {
    asm volatile("ldmatrix.sync.aligned.m8n8.x4.trans.shared.b16 {%0,%1,%2,%3}, [%4];"
                 : "=r"(d0), "=r"(d1), "=r"(d2), "=r"(d3) : "r"(a));
}

__device__ __forceinline__ void cp16(uint32_t dst, const void* src) {
    asm volatile("cp.async.cg.shared.global [%0], [%1], 16;"
                 :: "r"(dst), "l"(src) : "memory");
}
#define CP_COMMIT() asm volatile("cp.async.commit_group;" ::: "memory")
#define CP_WAIT1()  asm volatile("cp.async.wait_group 1;" ::: "memory")
#define CP_WAIT0()  asm volatile("cp.async.wait_group 0;" ::: "memory")

__device__ __forceinline__ void f2bf_split(float v, __nv_bfloat16& hi, __nv_bfloat16& lo) {
    hi = __float2bfloat16(v);
    lo = __float2bfloat16(v - __bfloat162float(hi));
}
__device__ __forceinline__ void f2h_split(float v, __half& hi, __half& lo) {
    hi = __float2half_rn(v);
    lo = __float2half_rn(v - __half2float(hi));
}

#define NT 512                  // 16 warps: 4x4 warp grid, warp tile 32x64

// ===========================================================================
// fp16 2-product GEMM engine (stages 0 and 3): D = Ah*Bh + Al*Bh
// smem per buffer (K-chunk 32, 80B row stride):
//   A_hi [128][80] @0 (10240)  A_lo @10240  B_hi [256][80] @20480 (20480)
// ===========================================================================
#define HRS    80
#define H_A_HI 0
#define H_A_LO 10240
#define H_B_HI 20480
#define H_BUFB 40960
#define SMEMB_H 131584          // stg 128*257*4; 3 buffers (122880) alias it

__device__ __forceinline__ void load_chunk_h(
    uint32_t smb, int cc, int bufIdx, int t,
    const __half* Ah, const __half* Al, const __half* Bh,
    long long aBase, long long bBase)
{
    const int kE = cc * 32;
    const uint32_t bo = (uint32_t)bufIdx * H_BUFB;
    {   // A: 128 rows x 4 segs (hi + lo)
        const int r = t >> 2, sg = t & 3;
        const long long off = aBase + (long long)r * DD + kE + sg * 8;
        const uint32_t d = smb + bo + H_A_HI + r * HRS + sg * 16;
        cp16(d, Ah + off);
        cp16(d + (H_A_LO - H_A_HI), Al + off);
    }
    // B: 256 rows x 4 segs (hi only)
    #pragma unroll
    for (int i = 0; i < 2; i++) {
        const int idx = t + i * NT;
        const int r = idx >> 2, sg = idx & 3;
        const long long off = bBase + (long long)r * DD + kE + sg * 8;
        cp16(smb + bo + H_B_HI + r * HRS + sg * 16, Bh + off);
    }
}

__device__ __forceinline__ void compute_chunk_h(
    uint32_t bufAdd, const uint32_t* aAddr, const uint32_t* bAddr,
    float (&acc)[2][8][4])
{
    #pragma unroll
    for (int kk = 0; kk < 2; kk++) {
        const uint32_t kb = bufAdd + (uint32_t)kk * 32u;
        uint32_t A[2][4], B0[8][2];
        #pragma unroll
        for (int fm = 0; fm < 2; fm++)
            ldsm_x4(A[fm][0], A[fm][1], A[fm][2], A[fm][3], aAddr[fm] + kb);
        #pragma unroll
        for (int p = 0; p < 4; p++)
            ldsm_x4(B0[2*p][0], B0[2*p][1], B0[2*p+1][0], B0[2*p+1][1],
                    bAddr[p] + kb);
        #pragma unroll
        for (int fm = 0; fm < 2; fm++)
            #pragma unroll
            for (int fn = 0; fn < 8; fn++)
                mma_fp16(acc[fm][fn], A[fm], B0[fn]);    // Ah*Bh
        #pragma unroll
        for (int fm = 0; fm < 2; fm++)
            ldsm_x4(A[fm][0], A[fm][1], A[fm][2], A[fm][3],
                    aAddr[fm] + kb + (H_A_LO - H_A_HI));
        #pragma unroll
        for (int fm = 0; fm < 2; fm++)
            #pragma unroll
            for (int fn = 0; fn < 8; fn++)
                mma_fp16(acc[fm][fn], A[fm], B0[fn]);    // Al*Bh
    }
}

// stage 0: A=x16, B=w16qk -> g_q/g_k bf16 hi/lo;  stage 3: A=ao16, B=w16o -> out
__global__ void __launch_bounds__(NT, 1) mma_gemm(int stage,
                                                  float* __restrict__ dOut,
                                                  const float* __restrict__ bias)
{
    extern __shared__ char sm[];
    const uint32_t smb = smem_u32(sm);
    const int t = threadIdx.x;
    const int lane = t & 31, wid = t >> 5;
    const int wm = wid & 3, wn = wid >> 2;
    const int g = lane >> 2, tg = lane & 3;

    const int n0 = blockIdx.x * 256;
    const int m0 = blockIdx.y * 128;

    const __half *Ah, *Al, *Bh;
    if (stage == 0) { Ah = g_x16_hi;  Al = g_x16_lo;  Bh = g_w16qk; }
    else            { Ah = g_ao16_hi; Al = g_ao16_lo; Bh = g_w16o; }
    const long long aBase = (long long)m0 * DD;
    const long long bBase = (long long)n0 * DD;

    uint32_t aAddr[2], bAddr[4];
    {
        const int rowA = lane & 15;
        const int khA  = (lane >> 4) * 16;
        #pragma unroll
        for (int fm = 0; fm < 2; fm++)
            aAddr[fm] = smb + H_A_HI + (uint32_t)((wm * 32 + fm * 16 + rowA) * HRS + khA);
        const int rowB = (lane & 7) + ((lane >> 4) & 1) * 8;
        const int khB  = ((lane >> 3) & 1) * 16;
        #pragma unroll
        for (int p = 0; p < 4; p++)
            bAddr[p] = smb + H_B_HI + (uint32_t)((wn * 64 + p * 16 + rowB) * HRS + khB);
    }

    float acc[2][8][4];
    #pragma unroll
    for (int i = 0; i < 2; i++)
        #pragma unroll
        for (int j = 0; j < 8; j++)
            #pragma unroll
            for (int e = 0; e < 4; e++) acc[i][j][e] = 0.f;

    const int NCH = 32;
    load_chunk_h(smb, 0, 0, t, Ah, Al, Bh, aBase, bBase);
    CP_COMMIT();
    load_chunk_h(smb, 1, 1, t, Ah, Al, Bh, aBase, bBase);
    CP_COMMIT();

    #pragma unroll 1
    for (int c = 0; c < NCH; c++) {
        CP_WAIT1();
        __syncthreads();
        compute_chunk_h((uint32_t)((c % 3) * H_BUFB), aAddr, bAddr, acc);
        const int cc = c + 2;
        if (cc < NCH)
            load_chunk_h(smb, cc, cc % 3, t, Ah, Al, Bh, aBase, bBase);
        CP_COMMIT();
    }
    __syncthreads();

    float* stg = (float*)sm;
    #pragma unroll
    for (int fm = 0; fm < 2; fm++) {
        const int r0 = wm * 32 + fm * 16 + g;
        #pragma unroll
        for (int fn = 0; fn < 8; fn++) {
            const int c0 = wn * 64 + fn * 8 + tg * 2;
            stg[r0 * 257 + c0]           = acc[fm][fn][0];
            stg[r0 * 257 + c0 + 1]       = acc[fm][fn][1];
            stg[(r0 + 8) * 257 + c0]     = acc[fm][fn][2];
            stg[(r0 + 8) * 257 + c0 + 1] = acc[fm][fn][3];
        }
    }
    __syncthreads();

    const int col = t & 255;
    const int rb  = t >> 8;
    if (stage == 0) {
        const bool isQ = (n0 < 1024);
        __nv_bfloat16* dh = isQ ? g_q_hi : g_k_hi;
        __nv_bfloat16* dl = isQ ? g_q_lo : g_k_lo;
        const int nq = isQ ? n0 : (n0 - 1024);
        #pragma unroll 4
        for (int rr = 0; rr < 64; rr++) {
            const int r = rb + rr * 2;
            float v = stg[r * 257 + col];
            __nv_bfloat16 hi, lo; f2bf_split(v, hi, lo);
            size_t o = (size_t)(m0 + r) * DD + nq + col;
            dh[o] = hi; dl[o] = lo;
        }
    } else {
        const float bv = bias[n0 + col];
        #pragma unroll 4
        for (int rr = 0; rr < 64; rr++) {
            const int r = rb + rr * 2;
            dOut[(size_t)(m0 + r) * DD + n0 + col] = stg[r * 257 + col] + bv;
        }
    }
}

// ===========================================================================
// bf16 3-product engine pieces (fused attention) — proven R14 code
// ===========================================================================
#define RS    80
#define A_HI  0
#define A_LO  10240
#define B_HI  20480
#define B_LO  40960
#define BUFB  61440
#define F_ATTN   133120
#define F_SLOT   33792
#define SMEMB_F  (F_ATTN + 2 * F_SLOT)   // 200704 (phase-A ring 3*61440 fits)

__device__ __forceinline__ void load_chunk_async(
    char* sm, uint32_t smb, int cc, int bufIdx, int w, int t,
    const __nv_bfloat16* Ah, const __nv_bfloat16* Al,
    const __nv_bfloat16* Bh, const __nv_bfloat16* Bl,
    long long aBase, long long bBase)
{
    const int kE = cc * 32;
    const uint32_t bo = (uint32_t)bufIdx * BUFB;
    const uint4 z = make_uint4(0u, 0u, 0u, 0u);
    {
        const int r = t >> 2, sg = t & 3;
        const long long off = aBase + (long long)r * DD + kE + sg * 8;
        const uint32_t d = smb + bo + A_HI + r * RS + sg * 16;
        cp16(d, Ah + off);
        cp16(d + (A_LO - A_HI), Al + off);
    }
    #pragma unroll
    for (int i = 0; i < 2; i++) {
        const int idx = t + i * NT;
        const int r = idx >> 2, sg = idx & 3;
        const bool v = (w > 0) || (r >= 128);
        const int o = B_HI + r * RS + sg * 16;
        if (v) {
            const long long off = bBase + (long long)r * DD + kE + sg * 8;
            cp16(smb + bo + o, Bh + off);
            cp16(smb + bo + o + (B_LO - B_HI), Bl + off);
        } else {
            *(uint4*)(sm + bo + o) = z;
            *(uint4*)(sm + bo + o + (B_LO - B_HI)) = z;
        }
    }
}

__device__ __forceinline__ void compute_chunk(
    uint32_t bufAdd, const uint32_t* aAddr, const uint32_t* bAddr,
    float (&acc)[2][8][4])
{
    #pragma unroll
    for (int kk = 0; kk < 2; kk++) {
        const uint32_t kb = bufAdd + (uint32_t)kk * 32u;
        uint32_t A[2][4], B0[8][2], B1[8][2];
        #pragma unroll
        for (int fm = 0; fm < 2; fm++)
            ldsm_x4(A[fm][0], A[fm][1], A[fm][2], A[fm][3], aAddr[fm] + kb);
        #pragma unroll
        for (int p = 0; p < 4; p++)
            ldsm_x4(B0[2*p][0], B0[2*p][1], B0[2*p+1][0], B0[2*p+1][1],
                    bAddr[p] + kb);
        #pragma unroll
        for (int fm = 0; fm < 2; fm++)
            #pragma unroll
            for (int fn = 0; fn < 8; fn++)
                mma_bf16(acc[fm][fn], A[fm], B0[fn]);    // Ah*Bh
        #pragma unroll
        for (int p = 0; p < 4; p++)
            ldsm_x4(B1[2*p][0], B1[2*p][1], B1[2*p+1][0], B1[2*p+1][1],
                    bAddr[p] + kb + (B_LO - B_HI));
        #pragma unroll
        for (int fm = 0; fm < 2; fm++)
            #pragma unroll
            for (int fn = 0; fn < 8; fn++)
                mma_bf16(acc[fm][fn], A[fm], B1[fn]);    // Ah*Bl
        #pragma unroll
        for (int fm = 0; fm < 2; fm++)
            ldsm_x4(A[fm][0], A[fm][1], A[fm][2], A[fm][3],
                    aAddr[fm] + kb + (A_LO - A_HI));
        #pragma unroll
        for (int fm = 0; fm < 2; fm++)
            #pragma unroll
            for (int fn = 0; fn < 8; fn++)
                mma_bf16(acc[fm][fn], A[fm], B0[fn]);    // Al*Bh
    }
}

__device__ __forceinline__ void load_pv_chunk(
    uint32_t smb, int b, int w, int n0, int cc, int slot, int t)
{
    const uint32_t sb = smb + F_ATTN + (uint32_t)slot * F_SLOT;
    #pragma unroll
    for (int i = 0; i < 2; i++) {
        const int idx = t + i * NT;
        const int r = idx >> 5, sg = idx & 31;
        const int tokLocal = cc * 32 + r;
        const bool v = (w > 0) || (tokLocal >= 128);
        const long long off =
            ((long long)b * NN + (long long)(w - 1) * WW + tokLocal) * DD + n0 + sg * 8;
        const __nv_bfloat16* sh = v ? (g_k_hi + off) : g_zero;
        const __nv_bfloat16* sl = v ? (g_k_lo + off) : g_zero;
        const uint32_t d = sb + (uint32_t)(r * 528 + sg * 16);
        cp16(d, sh);
        cp16(d + 16896, sl);
    }
}

__device__ __forceinline__ void compute_pv(
    uint32_t slotOff, uint32_t aOffC, const uint32_t* aA, const uint32_t* bT,
    float (&acc)[2][8][4])
{
    #pragma unroll
    for (int kk = 0; kk < 2; kk++) {
        const uint32_t ao = aOffC + (uint32_t)kk * 32u;
        const uint32_t bo = slotOff + (uint32_t)kk * 8448u;
        uint32_t A[2][4], B0[8][2], B1[8][2];
        #pragma unroll
        for (int fm = 0; fm < 2; fm++)
            ldsm_x4(A[fm][0], A[fm][1], A[fm][2], A[fm][3], aA[fm] + ao);
        #pragma unroll
        for (int p = 0; p < 4; p++)
            ldsm_x4_trans(B0[2*p][0], B0[2*p][1], B0[2*p+1][0], B0[2*p+1][1],
                          bT[p] + bo);
        #pragma unroll
        for (int fm = 0; fm < 2; fm++)
            #pragma unroll
            for (int fn = 0; fn < 8; fn++)
                mma_bf16(acc[fm][fn], A[fm], B0[fn]);
        #pragma unroll
        for (int p = 0; p < 4; p++)
            ldsm_x4_trans(B1[2*p][0], B1[2*p][1], B1[2*p+1][0], B1[2*p+1][1],
                          bT[p] + bo + 16896u);
        #pragma unroll
        for (int fm = 0; fm < 2; fm++)
            #pragma unroll
            for (int fn = 0; fn < 8; fn++)
                mma_bf16(acc[fm][fn], A[fm], B1[fn]);
        #pragma unroll
        for (int fm = 0; fm < 2; fm++)
            ldsm_x4(A[fm][0], A[fm][1], A[fm][2], A[fm][3],
                    aA[fm] + ao + 512u);
        #pragma unroll
        for (int fm = 0; fm < 2; fm++)
            #pragma unroll
            for (int fn = 0; fn < 8; fn++)
                mma_bf16(acc[fm][fn], A[fm], B0[fn]);
    }
}

__global__ void __launch_bounds__(NT, 1) fused_attn()
{
    extern __shared__ char sm[];
    const uint32_t smb = smem_u32(sm);
    const int t = threadIdx.x;
    const int lane = t & 31, wid = t >> 5;
    const int wm = wid & 3, wn = wid >> 2;
    const int g = lane >> 2, tg = lane & 3;
    const int w = blockIdx.x, b = blockIdx.y;

    const long long aBase = ((long long)b * NN + (long long)w * WW) * DD;
    const long long bBase = ((long long)b * NN + (long long)(w - 1) * WW) * DD;

    uint32_t aAddr[2], bAddr[4];
    {
        const int rowA = lane & 15;
        const int khA  = (lane >> 4) * 16;
        #pragma unroll
        for (int fm = 0; fm < 2; fm++)
            aAddr[fm] = smb + A_HI + (uint32_t)((wm * 32 + fm * 16 + rowA) * RS + khA);
        const int rowB = (lane & 7) + ((lane >> 4) & 1) * 8;
        const int khB  = ((lane >> 3) & 1) * 16;
        #pragma unroll
        for (int p = 0; p < 4; p++)
            bAddr[p] = smb + B_HI + (uint32_t)((wn * 64 + p * 16 + rowB) * RS + khB);
    }

    float acc[2][8][4];
    #pragma unroll
    for (int i = 0; i < 2; i++)
        #pragma unroll
        for (int j = 0; j < 8; j++)
            #pragma unroll
            for (int e = 0; e < 4; e++) acc[i][j][e] = 0.f;

    load_chunk_async(sm, smb, 0, 0, w, t, g_q_hi, g_q_lo, g_k_hi, g_k_lo, aBase, bBase);
    CP_COMMIT();
    load_chunk_async(sm, smb, 1, 1, w, t, g_q_hi, g_q_lo, g_k_hi, g_k_lo, aBase, bBase);
    CP_COMMIT();

    #pragma unroll 1
    for (int c = 0; c < 32; c++) {
        CP_WAIT1();
        __syncthreads();
        compute_chunk((uint32_t)((c % 3) * BUFB), aAddr, bAddr, acc);
        const int cc = c + 2;
        if (cc < 32)
            load_chunk_async(sm, smb, cc, cc % 3, w, t,
                             g_q_hi, g_q_lo, g_k_hi, g_k_lo, aBase, bBase);
        CP_COMMIT();
    }
    __syncthreads();

    float* stg = (float*)sm;
    #pragma unroll
    for (int fm = 0; fm < 2; fm++) {
        const int r0 = wm * 32 + fm * 16 + g;
        #pragma unroll
        for (int fn = 0; fn < 8; fn++) {
            const int c0 = wn * 64 + fn * 8 + tg * 2;
            stg[r0 * 260 + c0]           = acc[fm][fn][0];
            stg[r0 * 260 + c0 + 1]       = acc[fm][fn][1];
            stg[(r0 + 8) * 260 + c0]     = acc[fm][fn][2];
            stg[(r0 + 8) * 260 + c0 + 1] = acc[fm][fn][3];
        }
    }
    __syncthreads();

    for (int rr = 0; rr < 8; rr++) {
        const int r = wid * 8 + rr;
        float vv[8];
        float mx = -FLT_MAX;
        #pragma unroll
        for (int u = 0; u < 8; u++) {
            int j = lane + u * 32;
            float sc = stg[r * 260 + j] * 0.03125f;
            vv[u] = (j <= r + 128) ? sc : -FLT_MAX;
            mx = fmaxf(mx, vv[u]);
        }
        #pragma unroll
        for (int off = 16; off; off >>= 1)
            mx = fmaxf(mx, __shfl_xor_sync(0xffffffffu, mx, off));
        float sum = 0.f;
        #pragma unroll
        for (int u = 0; u < 8; u++) {
            int j = lane + u * 32;
            vv[u] = (j <= r + 128) ? expf(vv[u] - mx) : 0.f;
            sum += vv[u];
        }
        #pragma unroll
        for (int off = 16; off; off >>= 1)
            sum += __shfl_xor_sync(0xffffffffu, sum, off);
        const float inv = 1.f / sum;
        __nv_bfloat16* arow = (__nv_bfloat16*)(sm + (size_t)r * 1040);
        #pragma unroll
        for (int u = 0; u < 8; u++) {
            int j = lane + u * 32;
            __nv_bfloat16 hi, lo; f2bf_split(vv[u] * inv, hi, lo);
            arow[j]       = hi;
            arow[256 + j] = lo;
        }
    }
    __syncthreads();

    uint32_t aA[2], bT[4];
    {
        const int rowA = lane & 15;
        #pragma unroll
        for (int fm = 0; fm < 2; fm++)
            aA[fm] = smb + (uint32_t)((wm * 32 + fm * 16 + rowA) * 1040
                                      + ((lane >> 4) & 1) * 16);
        const int rowK = (lane & 7) + ((lane >> 3) & 1) * 8;
        const int dsel = ((lane >> 4) & 1) * 8;
        #pragma unroll
        for (int p = 0; p < 4; p++)
            bT[p] = smb + F_ATTN + (uint32_t)(rowK * 528
                                              + (wn * 64 + p * 16 + dsel) * 2);
    }

    #pragma unroll 1
    for (int niter = 0; niter < 4; niter++) {
        const int n0 = niter * 256;
        float acc2[2][8][4];
        #pragma unroll
        for (int i = 0; i < 2; i++)
            #pragma unroll
            for (int j = 0; j < 8; j++)
                #pragma unroll
                for (int e = 0; e < 4; e++) acc2[i][j][e] = 0.f;

        load_pv_chunk(smb, b, w, n0, 0, 0, t);
        CP_COMMIT();
        #pragma unroll 1
        for (int c = 0; c < 8; c++) {
            CP_WAIT0();
            __syncthreads();
            if (c < 7) {
                load_pv_chunk(smb, b, w, n0, c + 1, (c + 1) & 1, t);
                CP_COMMIT();
            }
            compute_pv((uint32_t)((c & 1) * F_SLOT), (uint32_t)(c * 64),
                       aA, bT, acc2);
        }

        // epilogue: split-store ao in fp16 hi/lo (consumed by fp16 stage 3)
        #pragma unroll
        for (int fm = 0; fm < 2; fm++) {
            const int r0 = wm * 32 + fm * 16 + g;
            #pragma unroll
            for (int fn = 0; fn < 8; fn++) {
                const int c0 = n0 + wn * 64 + fn * 8 + tg * 2;
                #pragma unroll
                for (int half = 0; half < 2; half++) {
                    const int r = r0 + half * 8;
                    __half h0, l0, h1, l1;
                    f2h_split(acc2[fm][fn][half * 2],     h0, l0);
                    f2h_split(acc2[fm][fn][half * 2 + 1], h1, l1);
                    const size_t o = ((size_t)b * NN + (size_t)w * WW + r) * DD + c0;
                    *(__half2*)(g_ao16_hi + o) = __halves2half2(h0, h1);
                    *(__half2*)(g_ao16_lo + o) = __halves2half2(l0, l1);
                }
            }
        }
    }
}

// ---------------------------------------------------------------------------
// Converters — destinations are device globals referenced IN DEVICE CODE ONLY
// ---------------------------------------------------------------------------
__global__ void convert_x_kernel(const float* __restrict__ x)
{
    size_t i = ((size_t)blockIdx.x * blockDim.x + threadIdx.x) * 4;
    float4 v = *(const float4*)(x + i);
    float vals[4] = { v.x, v.y, v.z, v.w };
    #pragma unroll
    for (int j = 0; j < 4; j++) {
        __half hi, lo; f2h_split(vals[j], hi, lo);
        g_x16_hi[i + j] = hi;
        g_x16_lo[i + j] = lo;
    }
}

// dst[n][k] = src[k][n], fp16 hi only; which: 0 -> wqk, 1 -> wo.
__global__ void transpose_convert_w(const float* __restrict__ src, int ld, int which)
{
    __half* dh = (which == 0) ? g_w16qk : g_w16o;
    __shared__ float sh[32][33];
    const int n0 = blockIdx.x * 32, k0 = blockIdx.y * 32;
    const int tx = threadIdx.x, ty = threadIdx.y;
    #pragma unroll
    for (int i = 0; i < 4; i++)
        sh[ty + 8 * i][tx] = src[(size_t)(k0 + ty + 8 * i) * ld + n0 + tx];
    __syncthreads();
    #pragma unroll
    for (int i = 0; i < 4; i++) {
        float v = sh[tx][ty + 8 * i];
        int n = n0 + ty + 8 * i, k = k0 + tx;
        dh[(size_t)n * DD + k] = __float2half_rn(v);
    }
}

// ---------------------------------------------------------------------------
extern "C" void kernel_launch(void* const* d_in, const int* in_sizes, int n_in,
                              void* d_out, int out_size)
{
    (void)in_sizes; (void)n_in; (void)out_size;
    const float* x     = (const float*)d_in[0];   // [4,4096,1024]
    const float* w_qkv = (const float*)d_in[1];   // [1024,3072]
    const float* w_out = (const float*)d_in[2];   // [1024,1024]
    const float* b_out = (const float*)d_in[3];   // [1024]
    float* out = (float*)d_out;                   // [4,4096,1024]

    cudaFuncSetAttribute(mma_gemm,   cudaFuncAttributeMaxDynamicSharedMemorySize, SMEMB_H);
    cudaFuncSetAttribute(fused_attn, cudaFuncAttributeMaxDynamicSharedMemorySize, SMEMB_F);

    // 1) split inputs: x -> fp16 hi/lo, weights -> fp16 hi
    convert_x_kernel<<<MTOT * DD / 1024, 256>>>(x);
    transpose_convert_w<<<dim3(64, 32), dim3(32, 8)>>>(w_qkv, 3072, 0);
    transpose_convert_w<<<dim3(32, 32), dim3(32, 8)>>>(w_out, 1024, 1);

    // 2) qk = x @ w_qkv[:, :2048]  (fp16 2-product) -> g_q/g_k bf16 hi/lo
    mma_gemm<<<dim3(8, 128), NT, SMEMB_H>>>(0, nullptr, nullptr);

    // 3) fused: sim = q@k2^T (bf16x3), softmax, ao = attn@k2 -> ao fp16 hi/lo
    fused_attn<<<dim3(NWIN, BB), NT, SMEMB_F>>>();

    // 4) out = ao @ w_out + b_out  (fp16 2-product)
    mma_gemm<<<dim3(4, 128), NT, SMEMB_H>>>(3, out, b_out);
}

// round 16
// speedup vs baseline: 1.5415x; 1.0685x over previous
#include <cuda_runtime.h>
#include <cuda_bf16.h>
#include <cuda_fp16.h>
#include <cstdint>
#include <math.h>
#include <float.h>

#define BB   4
#define NN   4096
#define DD   1024
#define WW   128
#define NWIN (NN / WW)          // 32
#define MTOT (BB * NN)          // 16384

// ---------------------------------------------------------------------------
// Scratch. ONLY referenced from device code — NEVER passed as kernel args from
// host (host-side &symbol is the shadow copy; GB300 ATS silently swallows it).
// Everything runs the fp16 2-product split now (A-side corrected, B-side hi).
// ---------------------------------------------------------------------------
__device__ __half g_x16_hi [(size_t)MTOT * DD];
__device__ __half g_x16_lo [(size_t)MTOT * DD];
__device__ __half g_w16qk  [(size_t)2048 * DD];   // [n][k] = w_qkv[k][n], hi only
__device__ __half g_w16o   [(size_t)1024 * DD];   // [n][k] = w_out[k][n], hi only
__device__ __half g_q16_hi [(size_t)MTOT * DD];
__device__ __half g_q16_lo [(size_t)MTOT * DD];
__device__ __half g_k16_hi [(size_t)MTOT * DD];
__device__ __half g_k16_lo [(size_t)MTOT * DD];
__device__ __half g_ao16_hi[(size_t)MTOT * DD];
__device__ __half g_ao16_lo[(size_t)MTOT * DD];
__device__ __align__(16) __half g_zero[16];       // zero-init BSS

// ---------------------------------------------------------------------------
// primitives
// ---------------------------------------------------------------------------
__device__ __forceinline__ uint32_t smem_u32(const void* p) {
    uint32_t a;
    asm("{ .reg .u64 t; cvta.to.shared.u64 t, %1; cvt.u32.u64 %0, t; }"
        : "=r"(a) : "l"(p));
    return a;
}

__device__ __forceinline__ void mma_fp16(float* c, const uint32_t* a, const uint32_t* b) {
    asm volatile(
        "mma.sync.aligned.m16n8k16.row.col.f32.f16.f16.f32 "
        "{%0,%1,%2,%3}, {%4,%5,%6,%7}, {%8,%9}, {%0,%1,%2,%3};"
        : "+f"(c[0]), "+f"(c[1]), "+f"(c[2]), "+f"(c[3])
        : "r"(a[0]), "r"(a[1]), "r"(a[2]), "r"(a[3]), "r"(b[0]), "r"(b[1]));
}

__device__ __forceinline__ void ldsm_x4(uint32_t& d0, uint32_t& d1,
                                        uint32_t& d2, uint32_t& d3, uint32_t a) {
    asm volatile("ldmatrix.sync.aligned.m8n8.x4.shared.b16 {%0,%1,%2,%3}, [%4];"
                 : "=r"(d0), "=r"(d1), "=r"(d2), "=r"(d3) : "r"(a));
}

__device__ __forceinline__ void ldsm_x4_trans(uint32_t& d0, uint32_t& d1,
                                              uint32_t& d2, uint32_t& d3, uint32_t a) {
    asm volatile("ldmatrix.sync.aligned.m8n8.x4.trans.shared.b16 {%0,%1,%2,%3}, [%4];"
                 : "=r"(d0), "=r"(d1), "=r"(d2), "=r"(d3) : "r"(a));
}

__device__ __forceinline__ void cp16(uint32_t dst, const void* src) {
    asm volatile("cp.async.cg.shared.global [%0], [%1], 16;"
                 :: "r"(dst), "l"(src) : "memory");
}
#define CP_COMMIT() asm volatile("cp.async.commit_group;" ::: "memory")
#define CP_WAIT1()  asm volatile("cp.async.wait_group 1;" ::: "memory")
#define CP_WAIT0()  asm volatile("cp.async.wait_group 0;" ::: "memory")

__device__ __forceinline__ void f2h_split(float v, __half& hi, __half& lo) {
    hi = __float2half_rn(v);
    lo = __float2half_rn(v - __half2float(hi));
}

#define NT 512                  // 16 warps: 4x4 warp grid, warp tile 32x64

// ===========================================================================
// fp16 2-product GEMM engine: D = Ah*Bh + Al*Bh
// smem per buffer (K-chunk 32, 80B row stride):
//   A_hi [128][80] @0 (10240)  A_lo @10240  B_hi [256][80] @20480 (20480)
// ===========================================================================
#define HRS    80
#define H_A_HI 0
#define H_A_LO 10240
#define H_B_HI 20480
#define H_BUFB 40960
#define SMEMB_H 131584          // stg 128*257*4; 3 buffers (122880) alias it

__device__ __forceinline__ void load_chunk_h(
    char* sm, uint32_t smb, int cc, int bufIdx, int t,
    const __half* Ah, const __half* Al, const __half* Bh,
    long long aBase, long long bBase, bool maskB, int w)
{
    const int kE = cc * 32;
    const uint32_t bo = (uint32_t)bufIdx * H_BUFB;
    {   // A: 128 rows x 4 segs (hi + lo)
        const int r = t >> 2, sg = t & 3;
        const long long off = aBase + (long long)r * DD + kE + sg * 8;
        const uint32_t d = smb + bo + H_A_HI + r * HRS + sg * 16;
        cp16(d, Ah + off);
        cp16(d + (H_A_LO - H_A_HI), Al + off);
    }
    // B: 256 rows x 4 segs (hi only)
    #pragma unroll
    for (int i = 0; i < 2; i++) {
        const int idx = t + i * NT;
        const int r = idx >> 2, sg = idx & 3;
        const int o = H_B_HI + r * HRS + sg * 16;
        const bool v = !maskB || (w > 0) || (r >= 128);
        if (v) {
            const long long off = bBase + (long long)r * DD + kE + sg * 8;
            cp16(smb + bo + o, Bh + off);
        } else {
            *(uint4*)(sm + bo + o) = make_uint4(0u, 0u, 0u, 0u);
        }
    }
}

__device__ __forceinline__ void compute_chunk_h(
    uint32_t bufAdd, const uint32_t* aAddr, const uint32_t* bAddr,
    float (&acc)[2][8][4])
{
    #pragma unroll
    for (int kk = 0; kk < 2; kk++) {
        const uint32_t kb = bufAdd + (uint32_t)kk * 32u;
        uint32_t A[2][4], B0[8][2];
        #pragma unroll
        for (int fm = 0; fm < 2; fm++)
            ldsm_x4(A[fm][0], A[fm][1], A[fm][2], A[fm][3], aAddr[fm] + kb);
        #pragma unroll
        for (int p = 0; p < 4; p++)
            ldsm_x4(B0[2*p][0], B0[2*p][1], B0[2*p+1][0], B0[2*p+1][1],
                    bAddr[p] + kb);
        #pragma unroll
        for (int fm = 0; fm < 2; fm++)
            #pragma unroll
            for (int fn = 0; fn < 8; fn++)
                mma_fp16(acc[fm][fn], A[fm], B0[fn]);    // Ah*Bh
        #pragma unroll
        for (int fm = 0; fm < 2; fm++)
            ldsm_x4(A[fm][0], A[fm][1], A[fm][2], A[fm][3],
                    aAddr[fm] + kb + (H_A_LO - H_A_HI));
        #pragma unroll
        for (int fm = 0; fm < 2; fm++)
            #pragma unroll
            for (int fn = 0; fn < 8; fn++)
                mma_fp16(acc[fm][fn], A[fm], B0[fn]);    // Al*Bh
    }
}

// stage 0: A=x16, B=w16qk -> g_q16/g_k16 hi/lo;  stage 3: A=ao16, B=w16o -> out
__global__ void __launch_bounds__(NT, 1) mma_gemm(int stage,
                                                  float* __restrict__ dOut,
                                                  const float* __restrict__ bias)
{
    extern __shared__ char sm[];
    const uint32_t smb = smem_u32(sm);
    const int t = threadIdx.x;
    const int lane = t & 31, wid = t >> 5;
    const int wm = wid & 3, wn = wid >> 2;
    const int g = lane >> 2, tg = lane & 3;

    const int n0 = blockIdx.x * 256;
    const int m0 = blockIdx.y * 128;

    const __half *Ah, *Al, *Bh;
    if (stage == 0) { Ah = g_x16_hi;  Al = g_x16_lo;  Bh = g_w16qk; }
    else            { Ah = g_ao16_hi; Al = g_ao16_lo; Bh = g_w16o; }
    const long long aBase = (long long)m0 * DD;
    const long long bBase = (long long)n0 * DD;

    uint32_t aAddr[2], bAddr[4];
    {
        const int rowA = lane & 15;
        const int khA  = (lane >> 4) * 16;
        #pragma unroll
        for (int fm = 0; fm < 2; fm++)
            aAddr[fm] = smb + H_A_HI + (uint32_t)((wm * 32 + fm * 16 + rowA) * HRS + khA);
        const int rowB = (lane & 7) + ((lane >> 4) & 1) * 8;
        const int khB  = ((lane >> 3) & 1) * 16;
        #pragma unroll
        for (int p = 0; p < 4; p++)
            bAddr[p] = smb + H_B_HI + (uint32_t)((wn * 64 + p * 16 + rowB) * HRS + khB);
    }

    float acc[2][8][4];
    #pragma unroll
    for (int i = 0; i < 2; i++)
        #pragma unroll
        for (int j = 0; j < 8; j++)
            #pragma unroll
            for (int e = 0; e < 4; e++) acc[i][j][e] = 0.f;

    const int NCH = 32;
    load_chunk_h(sm, smb, 0, 0, t, Ah, Al, Bh, aBase, bBase, false, 0);
    CP_COMMIT();
    load_chunk_h(sm, smb, 1, 1, t, Ah, Al, Bh, aBase, bBase, false, 0);
    CP_COMMIT();

    #pragma unroll 1
    for (int c = 0; c < NCH; c++) {
        CP_WAIT1();
        __syncthreads();
        compute_chunk_h((uint32_t)((c % 3) * H_BUFB), aAddr, bAddr, acc);
        const int cc = c + 2;
        if (cc < NCH)
            load_chunk_h(sm, smb, cc, cc % 3, t, Ah, Al, Bh, aBase, bBase, false, 0);
        CP_COMMIT();
    }
    __syncthreads();

    float* stg = (float*)sm;
    #pragma unroll
    for (int fm = 0; fm < 2; fm++) {
        const int r0 = wm * 32 + fm * 16 + g;
        #pragma unroll
        for (int fn = 0; fn < 8; fn++) {
            const int c0 = wn * 64 + fn * 8 + tg * 2;
            stg[r0 * 257 + c0]           = acc[fm][fn][0];
            stg[r0 * 257 + c0 + 1]       = acc[fm][fn][1];
            stg[(r0 + 8) * 257 + c0]     = acc[fm][fn][2];
            stg[(r0 + 8) * 257 + c0 + 1] = acc[fm][fn][3];
        }
    }
    __syncthreads();

    const int col = t & 255;
    const int rb  = t >> 8;
    if (stage == 0) {
        const bool isQ = (n0 < 1024);
        __half* dh = isQ ? g_q16_hi : g_k16_hi;
        __half* dl = isQ ? g_q16_lo : g_k16_lo;
        const int nq = isQ ? n0 : (n0 - 1024);
        #pragma unroll 4
        for (int rr = 0; rr < 64; rr++) {
            const int r = rb + rr * 2;
            float v = stg[r * 257 + col];
            __half hi, lo; f2h_split(v, hi, lo);
            size_t o = (size_t)(m0 + r) * DD + nq + col;
            dh[o] = hi; dl[o] = lo;
        }
    } else {
        const float bv = bias[n0 + col];
        #pragma unroll 4
        for (int rr = 0; rr < 64; rr++) {
            const int r = rb + rr * 2;
            dOut[(size_t)(m0 + r) * DD + n0 + col] = stg[r * 257 + col] + bv;
        }
    }
}

// ===========================================================================
// Fused attention (fp16 2-product): one CTA per (w, b).
// Phase A: sim = q @ k2^T (A=q hi/lo, B=k hi), softmax -> attn fp16 hi/lo smem
// Phase B: ao = attn @ k2 via ldmatrix.trans on k2 hi (A=attn hi/lo)
// smem map: phase-A ring 3 x 40960 @ [0,122880); stg 128x1040B @ [0,133120)
//           PV slots 2 x 16896 @ [133120, 166912)
// ===========================================================================
#define F_PV    133120
#define F_SLOT  16896
#define SMEMB_F (F_PV + 2 * F_SLOT)   // 166912

__device__ __forceinline__ void load_pv_chunk(
    uint32_t smb, int b, int w, int n0, int cc, int slot, int t)
{
    const uint32_t sb = smb + F_PV + (uint32_t)slot * F_SLOT;
    #pragma unroll
    for (int i = 0; i < 2; i++) {
        const int idx = t + i * NT;           // 1024 segs: 32 rows x 32 segs
        const int r = idx >> 5, sg = idx & 31;
        const int tokLocal = cc * 32 + r;
        const bool v = (w > 0) || (tokLocal >= 128);
        const long long off =
            ((long long)b * NN + (long long)(w - 1) * WW + tokLocal) * DD + n0 + sg * 8;
        const __half* sh = v ? (g_k16_hi + off) : g_zero;
        cp16(sb + (uint32_t)(r * 528 + sg * 16), sh);
    }
}

__device__ __forceinline__ void compute_pv(
    uint32_t slotOff, uint32_t aOffC, const uint32_t* aA, const uint32_t* bT,
    float (&acc)[2][8][4])
{
    #pragma unroll
    for (int kk = 0; kk < 2; kk++) {
        const uint32_t ao = aOffC + (uint32_t)kk * 32u;        // key bytes
        const uint32_t bo = slotOff + (uint32_t)kk * 8448u;    // 16 rows * 528
        uint32_t A[2][4], B0[8][2];
        #pragma unroll
        for (int fm = 0; fm < 2; fm++)
            ldsm_x4(A[fm][0], A[fm][1], A[fm][2], A[fm][3], aA[fm] + ao);
        #pragma unroll
        for (int p = 0; p < 4; p++)
            ldsm_x4_trans(B0[2*p][0], B0[2*p][1], B0[2*p+1][0], B0[2*p+1][1],
                          bT[p] + bo);
        #pragma unroll
        for (int fm = 0; fm < 2; fm++)
            #pragma unroll
            for (int fn = 0; fn < 8; fn++)
                mma_fp16(acc[fm][fn], A[fm], B0[fn]);   // Ah*Bh
        #pragma unroll
        for (int fm = 0; fm < 2; fm++)
            ldsm_x4(A[fm][0], A[fm][1], A[fm][2], A[fm][3],
                    aA[fm] + ao + 512u);
        #pragma unroll
        for (int fm = 0; fm < 2; fm++)
            #pragma unroll
            for (int fn = 0; fn < 8; fn++)
                mma_fp16(acc[fm][fn], A[fm], B0[fn]);   // Al*Bh
    }
}

__global__ void __launch_bounds__(NT, 1) fused_attn()
{
    extern __shared__ char sm[];
    const uint32_t smb = smem_u32(sm);
    const int t = threadIdx.x;
    const int lane = t & 31, wid = t >> 5;
    const int wm = wid & 3, wn = wid >> 2;
    const int g = lane >> 2, tg = lane & 3;
    const int w = blockIdx.x, b = blockIdx.y;

    // ---- Phase A: sim = q @ k2^T (fp16 2-product, B=k hi with w==0 mask) ----
    const long long aBase = ((long long)b * NN + (long long)w * WW) * DD;
    const long long bBase = ((long long)b * NN + (long long)(w - 1) * WW) * DD;

    uint32_t aAddr[2], bAddr[4];
    {
        const int rowA = lane & 15;
        const int khA  = (lane >> 4) * 16;
        #pragma unroll
        for (int fm = 0; fm < 2; fm++)
            aAddr[fm] = smb + H_A_HI + (uint32_t)((wm * 32 + fm * 16 + rowA) * HRS + khA);
        const int rowB = (lane & 7) + ((lane >> 4) & 1) * 8;
        const int khB  = ((lane >> 3) & 1) * 16;
        #pragma unroll
        for (int p = 0; p < 4; p++)
            bAddr[p] = smb + H_B_HI + (uint32_t)((wn * 64 + p * 16 + rowB) * HRS + khB);
    }

    float acc[2][8][4];
    #pragma unroll
    for (int i = 0; i < 2; i++)
        #pragma unroll
        for (int j = 0; j < 8; j++)
            #pragma unroll
            for (int e = 0; e < 4; e++) acc[i][j][e] = 0.f;

    load_chunk_h(sm, smb, 0, 0, t, g_q16_hi, g_q16_lo, g_k16_hi, aBase, bBase, true, w);
    CP_COMMIT();
    load_chunk_h(sm, smb, 1, 1, t, g_q16_hi, g_q16_lo, g_k16_hi, aBase, bBase, true, w);
    CP_COMMIT();

    #pragma unroll 1
    for (int c = 0; c < 32; c++) {
        CP_WAIT1();
        __syncthreads();
        compute_chunk_h((uint32_t)((c % 3) * H_BUFB), aAddr, bAddr, acc);
        const int cc = c + 2;
        if (cc < 32)
            load_chunk_h(sm, smb, cc, cc % 3, t,
                         g_q16_hi, g_q16_lo, g_k16_hi, aBase, bBase, true, w);
        CP_COMMIT();
    }
    __syncthreads();

    // ---- stage acc -> stg [128][260] fp32 (row stride 1040B) ----
    float* stg = (float*)sm;
    #pragma unroll
    for (int fm = 0; fm < 2; fm++) {
        const int r0 = wm * 32 + fm * 16 + g;
        #pragma unroll
        for (int fn = 0; fn < 8; fn++) {
            const int c0 = wn * 64 + fn * 8 + tg * 2;
            stg[r0 * 260 + c0]           = acc[fm][fn][0];
            stg[r0 * 260 + c0 + 1]       = acc[fm][fn][1];
            stg[(r0 + 8) * 260 + c0]     = acc[fm][fn][2];
            stg[(r0 + 8) * 260 + c0 + 1] = acc[fm][fn][3];
        }
    }
    __syncthreads();

    // ---- softmax -> attn fp16: hi @ row+0, lo @ row+512 (in-place) ----
    for (int rr = 0; rr < 8; rr++) {
        const int r = wid * 8 + rr;
        float vv[8];
        float mx = -FLT_MAX;
        #pragma unroll
        for (int u = 0; u < 8; u++) {
            int j = lane + u * 32;
            float sc = stg[r * 260 + j] * 0.03125f;
            vv[u] = (j <= r + 128) ? sc : -FLT_MAX;
            mx = fmaxf(mx, vv[u]);
        }
        #pragma unroll
        for (int off = 16; off; off >>= 1)
            mx = fmaxf(mx, __shfl_xor_sync(0xffffffffu, mx, off));
        float sum = 0.f;
        #pragma unroll
        for (int u = 0; u < 8; u++) {
            int j = lane + u * 32;
            vv[u] = (j <= r + 128) ? expf(vv[u] - mx) : 0.f;
            sum += vv[u];
        }
        #pragma unroll
        for (int off = 16; off; off >>= 1)
            sum += __shfl_xor_sync(0xffffffffu, sum, off);
        const float inv = 1.f / sum;
        __half* arow = (__half*)(sm + (size_t)r * 1040);
        #pragma unroll
        for (int u = 0; u < 8; u++) {
            int j = lane + u * 32;
            __half hi, lo; f2h_split(vv[u] * inv, hi, lo);
            arow[j]       = hi;
            arow[256 + j] = lo;     // +512 bytes
        }
    }
    __syncthreads();

    // ---- Phase B: ao = attn @ k2 (fp16 2-product), 4 N-iters of 256 dims ----
    uint32_t aA[2], bT[4];
    {
        const int rowA = lane & 15;
        #pragma unroll
        for (int fm = 0; fm < 2; fm++)
            aA[fm] = smb + (uint32_t)((wm * 32 + fm * 16 + rowA) * 1040
                                      + ((lane >> 4) & 1) * 16);
        const int rowK = (lane & 7) + ((lane >> 3) & 1) * 8;
        const int dsel = ((lane >> 4) & 1) * 8;
        #pragma unroll
        for (int p = 0; p < 4; p++)
            bT[p] = smb + F_PV + (uint32_t)(rowK * 528
                                            + (wn * 64 + p * 16 + dsel) * 2);
    }

    #pragma unroll 1
    for (int niter = 0; niter < 4; niter++) {
        const int n0 = niter * 256;
        float acc2[2][8][4];
        #pragma unroll
        for (int i = 0; i < 2; i++)
            #pragma unroll
            for (int j = 0; j < 8; j++)
                #pragma unroll
                for (int e = 0; e < 4; e++) acc2[i][j][e] = 0.f;

        load_pv_chunk(smb, b, w, n0, 0, 0, t);
        CP_COMMIT();
        #pragma unroll 1
        for (int c = 0; c < 8; c++) {
            CP_WAIT0();
            __syncthreads();
            if (c < 7) {
                load_pv_chunk(smb, b, w, n0, c + 1, (c + 1) & 1, t);
                CP_COMMIT();
            }
            compute_pv((uint32_t)((c & 1) * F_SLOT), (uint32_t)(c * 64),
                       aA, bT, acc2);
        }

        // epilogue: split-store ao in fp16 hi/lo (consumed by fp16 stage 3)
        #pragma unroll
        for (int fm = 0; fm < 2; fm++) {
            const int r0 = wm * 32 + fm * 16 + g;
            #pragma unroll
            for (int fn = 0; fn < 8; fn++) {
                const int c0 = n0 + wn * 64 + fn * 8 + tg * 2;
                #pragma unroll
                for (int half = 0; half < 2; half++) {
                    const int r = r0 + half * 8;
                    __half h0, l0, h1, l1;
                    f2h_split(acc2[fm][fn][half * 2],     h0, l0);
                    f2h_split(acc2[fm][fn][half * 2 + 1], h1, l1);
                    const size_t o = ((size_t)b * NN + (size_t)w * WW + r) * DD + c0;
                    *(__half2*)(g_ao16_hi + o) = __halves2half2(h0, h1);
                    *(__half2*)(g_ao16_lo + o) = __halves2half2(l0, l1);
                }
            }
        }
    }
}

// ---------------------------------------------------------------------------
// Converters — destinations are device globals referenced IN DEVICE CODE ONLY
// ---------------------------------------------------------------------------
__global__ void convert_x_kernel(const float* __restrict__ x)
{
    size_t i = ((size_t)blockIdx.x * blockDim.x + threadIdx.x) * 4;
    float4 v = *(const float4*)(x + i);
    float vals[4] = { v.x, v.y, v.z, v.w };
    #pragma unroll
    for (int j = 0; j < 4; j++) {
        __half hi, lo; f2h_split(vals[j], hi, lo);
        g_x16_hi[i + j] = hi;
        g_x16_lo[i + j] = lo;
    }
}

// dst[n][k] = src[k][n], fp16 hi only; which: 0 -> wqk, 1 -> wo.
__global__ void transpose_convert_w(const float* __restrict__ src, int ld, int which)
{
    __half* dh = (which == 0) ? g_w16qk : g_w16o;
    __shared__ float sh[32][33];
    const int n0 = blockIdx.x * 32, k0 = blockIdx.y * 32;
    const int tx = threadIdx.x, ty = threadIdx.y;
    #pragma unroll
    for (int i = 0; i < 4; i++)
        sh[ty + 8 * i][tx] = src[(size_t)(k0 + ty + 8 * i) * ld + n0 + tx];
    __syncthreads();
    #pragma unroll
    for (int i = 0; i < 4; i++) {
        float v = sh[tx][ty + 8 * i];
        int n = n0 + ty + 8 * i, k = k0 + tx;
        dh[(size_t)n * DD + k] = __float2half_rn(v);
    }
}

// ---------------------------------------------------------------------------
extern "C" void kernel_launch(void* const* d_in, const int* in_sizes, int n_in,
                              void* d_out, int out_size)
{
    (void)in_sizes; (void)n_in; (void)out_size;
    const float* x     = (const float*)d_in[0];   // [4,4096,1024]
    const float* w_qkv = (const float*)d_in[1];   // [1024,3072]
    const float* w_out = (const float*)d_in[2];   // [1024,1024]
    const float* b_out = (const float*)d_in[3];   // [1024]
    float* out = (float*)d_out;                   // [4,4096,1024]

    cudaFuncSetAttribute(mma_gemm,   cudaFuncAttributeMaxDynamicSharedMemorySize, SMEMB_H);
    cudaFuncSetAttribute(fused_attn, cudaFuncAttributeMaxDynamicSharedMemorySize, SMEMB_F);

    // 1) split inputs: x -> fp16 hi/lo, weights -> fp16 hi
    convert_x_kernel<<<MTOT * DD / 1024, 256>>>(x);
    transpose_convert_w<<<dim3(64, 32), dim3(32, 8)>>>(w_qkv, 3072, 0);
    transpose_convert_w<<<dim3(32, 32), dim3(32, 8)>>>(w_out, 1024, 1);

    // 2) qk = x @ w_qkv[:, :2048]  (fp16 2-product) -> g_q16/g_k16 hi/lo
    mma_gemm<<<dim3(8, 128), NT, SMEMB_H>>>(0, nullptr, nullptr);

    // 3) fused attention (fp16 2-product; values==keys per reference bug)
    fused_attn<<<dim3(NWIN, BB), NT, SMEMB_F>>>();

    // 4) out = ao @ w_out + b_out  (fp16 2-product)
    mma_gemm<<<dim3(4, 128), NT, SMEMB_H>>>(3, out, b_out);
}

// round 17
// speedup vs baseline: 2.6426x; 1.7143x over previous
#include <cuda_runtime.h>
#include <cuda_fp16.h>
#include <cstdint>
#include <math.h>
#include <float.h>

#define BB   4
#define NN   4096
#define DD   1024
#define WW   128
#define NWIN (NN / WW)          // 32
#define MTOT (BB * NN)          // 16384

// ---------------------------------------------------------------------------
// Scratch. ONLY referenced from device code — NEVER passed as kernel args from
// host (host-side &symbol is the shadow copy; GB300 ATS silently swallows it).
// Plain fp16 pipeline (single product per matmul).
// ---------------------------------------------------------------------------
__device__ __half g_x16  [(size_t)MTOT * DD];
__device__ __half g_w16qk[(size_t)2048 * DD];   // [n][k] = w_qkv[k][n]
__device__ __half g_w16o [(size_t)1024 * DD];   // [n][k] = w_out[k][n]
__device__ __half g_q16  [(size_t)MTOT * DD];
__device__ __half g_k16  [(size_t)MTOT * DD];
__device__ __half g_ao16 [(size_t)MTOT * DD];
__device__ __align__(16) __half g_zero[16];     // zero-init BSS

// ---------------------------------------------------------------------------
// primitives
// ---------------------------------------------------------------------------
__device__ __forceinline__ uint32_t smem_u32(const void* p) {
    uint32_t a;
    asm("{ .reg .u64 t; cvta.to.shared.u64 t, %1; cvt.u32.u64 %0, t; }"
        : "=r"(a) : "l"(p));
    return a;
}

__device__ __forceinline__ void mma_fp16(float* c, const uint32_t* a, const uint32_t* b) {
    asm volatile(
        "mma.sync.aligned.m16n8k16.row.col.f32.f16.f16.f32 "
        "{%0,%1,%2,%3}, {%4,%5,%6,%7}, {%8,%9}, {%0,%1,%2,%3};"
        : "+f"(c[0]), "+f"(c[1]), "+f"(c[2]), "+f"(c[3])
        : "r"(a[0]), "r"(a[1]), "r"(a[2]), "r"(a[3]), "r"(b[0]), "r"(b[1]));
}

__device__ __forceinline__ void ldsm_x4(uint32_t& d0, uint32_t& d1,
                                        uint32_t& d2, uint32_t& d3, uint32_t a) {
    asm volatile("ldmatrix.sync.aligned.m8n8.x4.shared.b16 {%0,%1,%2,%3}, [%4];"
                 : "=r"(d0), "=r"(d1), "=r"(d2), "=r"(d3) : "r"(a));
}

__device__ __forceinline__ void ldsm_x4_trans(uint32_t& d0, uint32_t& d1,
                                              uint32_t& d2, uint32_t& d3, uint32_t a) {
    asm volatile("ldmatrix.sync.aligned.m8n8.x4.trans.shared.b16 {%0,%1,%2,%3}, [%4];"
                 : "=r"(d0), "=r"(d1), "=r"(d2), "=r"(d3) : "r"(a));
}

__device__ __forceinline__ void cp16(uint32_t dst, const void* src) {
    asm volatile("cp.async.cg.shared.global [%0], [%1], 16;"
                 :: "r"(dst), "l"(src) : "memory");
}
#define CP_COMMIT() asm volatile("cp.async.commit_group;" ::: "memory")
#define CP_WAIT1()  asm volatile("cp.async.wait_group 1;" ::: "memory")
#define CP_WAIT0()  asm volatile("cp.async.wait_group 0;" ::: "memory")

#define NT 512                  // 16 warps: 4x4 warp grid, warp tile 32x64

// ===========================================================================
// fp16 single-product GEMM engine: D = A*B
// smem per buffer (K-chunk 32, 80B row stride):
//   A [128][80] @0 (10240)   B [256][80] @10240 (20480)
// ===========================================================================
#define HRS    80
#define H_A    0
#define H_B    10240
#define H_BUFB 30720
#define SMEMB_H 131584          // stg 128*257*4; 3 buffers (92160) alias it

__device__ __forceinline__ void load_chunk_h(
    char* sm, uint32_t smb, int cc, int bufIdx, int t,
    const __half* A, const __half* B,
    long long aBase, long long bBase, bool maskB, int w)
{
    const int kE = cc * 32;
    const uint32_t bo = (uint32_t)bufIdx * H_BUFB;
    {   // A: 128 rows x 4 segs
        const int r = t >> 2, sg = t & 3;
        const long long off = aBase + (long long)r * DD + kE + sg * 8;
        cp16(smb + bo + H_A + r * HRS + sg * 16, A + off);
    }
    // B: 256 rows x 4 segs
    #pragma unroll
    for (int i = 0; i < 2; i++) {
        const int idx = t + i * NT;
        const int r = idx >> 2, sg = idx & 3;
        const int o = H_B + r * HRS + sg * 16;
        const bool v = !maskB || (w > 0) || (r >= 128);
        if (v) {
            const long long off = bBase + (long long)r * DD + kE + sg * 8;
            cp16(smb + bo + o, B + off);
        } else {
            *(uint4*)(sm + bo + o) = make_uint4(0u, 0u, 0u, 0u);
        }
    }
}

__device__ __forceinline__ void compute_chunk_h(
    uint32_t bufAdd, const uint32_t* aAddr, const uint32_t* bAddr,
    float (&acc)[2][8][4])
{
    #pragma unroll
    for (int kk = 0; kk < 2; kk++) {
        const uint32_t kb = bufAdd + (uint32_t)kk * 32u;
        uint32_t A[2][4], B0[8][2];
        #pragma unroll
        for (int fm = 0; fm < 2; fm++)
            ldsm_x4(A[fm][0], A[fm][1], A[fm][2], A[fm][3], aAddr[fm] + kb);
        #pragma unroll
        for (int p = 0; p < 4; p++)
            ldsm_x4(B0[2*p][0], B0[2*p][1], B0[2*p+1][0], B0[2*p+1][1],
                    bAddr[p] + kb);
        #pragma unroll
        for (int fm = 0; fm < 2; fm++)
            #pragma unroll
            for (int fn = 0; fn < 8; fn++)
                mma_fp16(acc[fm][fn], A[fm], B0[fn]);
    }
}

// stage 0: A=x16, B=w16qk -> g_q16/g_k16;  stage 3: A=ao16, B=w16o -> out
__global__ void __launch_bounds__(NT, 1) mma_gemm(int stage,
                                                  float* __restrict__ dOut,
                                                  const float* __restrict__ bias)
{
    extern __shared__ char sm[];
    const uint32_t smb = smem_u32(sm);
    const int t = threadIdx.x;
    const int lane = t & 31, wid = t >> 5;
    const int wm = wid & 3, wn = wid >> 2;
    const int g = lane >> 2, tg = lane & 3;

    const int n0 = blockIdx.x * 256;
    const int m0 = blockIdx.y * 128;

    const __half *A, *B;
    if (stage == 0) { A = g_x16;  B = g_w16qk; }
    else            { A = g_ao16; B = g_w16o; }
    const long long aBase = (long long)m0 * DD;
    const long long bBase = (long long)n0 * DD;

    uint32_t aAddr[2], bAddr[4];
    {
        const int rowA = lane & 15;
        const int khA  = (lane >> 4) * 16;
        #pragma unroll
        for (int fm = 0; fm < 2; fm++)
            aAddr[fm] = smb + H_A + (uint32_t)((wm * 32 + fm * 16 + rowA) * HRS + khA);
        const int rowB = (lane & 7) + ((lane >> 4) & 1) * 8;
        const int khB  = ((lane >> 3) & 1) * 16;
        #pragma unroll
        for (int p = 0; p < 4; p++)
            bAddr[p] = smb + H_B + (uint32_t)((wn * 64 + p * 16 + rowB) * HRS + khB);
    }

    float acc[2][8][4];
    #pragma unroll
    for (int i = 0; i < 2; i++)
        #pragma unroll
        for (int j = 0; j < 8; j++)
            #pragma unroll
            for (int e = 0; e < 4; e++) acc[i][j][e] = 0.f;

    const int NCH = 32;
    load_chunk_h(sm, smb, 0, 0, t, A, B, aBase, bBase, false, 0);
    CP_COMMIT();
    load_chunk_h(sm, smb, 1, 1, t, A, B, aBase, bBase, false, 0);
    CP_COMMIT();

    #pragma unroll 1
    for (int c = 0; c < NCH; c++) {
        CP_WAIT1();
        __syncthreads();
        compute_chunk_h((uint32_t)((c % 3) * H_BUFB), aAddr, bAddr, acc);
        const int cc = c + 2;
        if (cc < NCH)
            load_chunk_h(sm, smb, cc, cc % 3, t, A, B, aBase, bBase, false, 0);
        CP_COMMIT();
    }
    __syncthreads();

    float* stg = (float*)sm;
    #pragma unroll
    for (int fm = 0; fm < 2; fm++) {
        const int r0 = wm * 32 + fm * 16 + g;
        #pragma unroll
        for (int fn = 0; fn < 8; fn++) {
            const int c0 = wn * 64 + fn * 8 + tg * 2;
            stg[r0 * 257 + c0]           = acc[fm][fn][0];
            stg[r0 * 257 + c0 + 1]       = acc[fm][fn][1];
            stg[(r0 + 8) * 257 + c0]     = acc[fm][fn][2];
            stg[(r0 + 8) * 257 + c0 + 1] = acc[fm][fn][3];
        }
    }
    __syncthreads();

    const int col = t & 255;
    const int rb  = t >> 8;
    if (stage == 0) {
        __half* dst = (n0 < 1024) ? g_q16 : g_k16;
        const int nq = (n0 < 1024) ? n0 : (n0 - 1024);
        #pragma unroll 4
        for (int rr = 0; rr < 64; rr++) {
            const int r = rb + rr * 2;
            dst[(size_t)(m0 + r) * DD + nq + col] =
                __float2half_rn(stg[r * 257 + col]);
        }
    } else {
        const float bv = bias[n0 + col];
        #pragma unroll 4
        for (int rr = 0; rr < 64; rr++) {
            const int r = rb + rr * 2;
            dOut[(size_t)(m0 + r) * DD + n0 + col] = stg[r * 257 + col] + bv;
        }
    }
}

// ===========================================================================
// Fused attention (plain fp16): one CTA per (w, b).
// Phase A: sim = q @ k2^T, softmax -> attn fp16 in smem
// Phase B: ao = attn @ k2 via ldmatrix.trans on k2 tiles
// smem map: phase-A ring 3 x 30720 @ [0,92160); stg 128x1040B @ [0,133120)
//           PV slots 2 x 16896 @ [133120, 166912)
// ===========================================================================
#define F_PV    133120
#define F_SLOT  16896
#define SMEMB_F (F_PV + 2 * F_SLOT)   // 166912

__device__ __forceinline__ void load_pv_chunk(
    uint32_t smb, int b, int w, int n0, int cc, int slot, int t)
{
    const uint32_t sb = smb + F_PV + (uint32_t)slot * F_SLOT;
    #pragma unroll
    for (int i = 0; i < 2; i++) {
        const int idx = t + i * NT;           // 1024 segs: 32 rows x 32 segs
        const int r = idx >> 5, sg = idx & 31;
        const int tokLocal = cc * 32 + r;
        const bool v = (w > 0) || (tokLocal >= 128);
        const long long off =
            ((long long)b * NN + (long long)(w - 1) * WW + tokLocal) * DD + n0 + sg * 8;
        const __half* sh = v ? (g_k16 + off) : g_zero;
        cp16(sb + (uint32_t)(r * 528 + sg * 16), sh);
    }
}

__device__ __forceinline__ void compute_pv(
    uint32_t slotOff, uint32_t aOffC, const uint32_t* aA, const uint32_t* bT,
    float (&acc)[2][8][4])
{
    #pragma unroll
    for (int kk = 0; kk < 2; kk++) {
        const uint32_t ao = aOffC + (uint32_t)kk * 32u;        // key bytes
        const uint32_t bo = slotOff + (uint32_t)kk * 8448u;    // 16 rows * 528
        uint32_t A[2][4], B0[8][2];
        #pragma unroll
        for (int fm = 0; fm < 2; fm++)
            ldsm_x4(A[fm][0], A[fm][1], A[fm][2], A[fm][3], aA[fm] + ao);
        #pragma unroll
        for (int p = 0; p < 4; p++)
            ldsm_x4_trans(B0[2*p][0], B0[2*p][1], B0[2*p+1][0], B0[2*p+1][1],
                          bT[p] + bo);
        #pragma unroll
        for (int fm = 0; fm < 2; fm++)
            #pragma unroll
            for (int fn = 0; fn < 8; fn++)
                mma_fp16(acc[fm][fn], A[fm], B0[fn]);
    }
}

__global__ void __launch_bounds__(NT, 1) fused_attn()
{
    extern __shared__ char sm[];
    const uint32_t smb = smem_u32(sm);
    const int t = threadIdx.x;
    const int lane = t & 31, wid = t >> 5;
    const int wm = wid & 3, wn = wid >> 2;
    const int g = lane >> 2, tg = lane & 3;
    const int w = blockIdx.x, b = blockIdx.y;

    // ---- Phase A: sim = q @ k2^T ----
    const long long aBase = ((long long)b * NN + (long long)w * WW) * DD;
    const long long bBase = ((long long)b * NN + (long long)(w - 1) * WW) * DD;

    uint32_t aAddr[2], bAddr[4];
    {
        const int rowA = lane & 15;
        const int khA  = (lane >> 4) * 16;
        #pragma unroll
        for (int fm = 0; fm < 2; fm++)
            aAddr[fm] = smb + H_A + (uint32_t)((wm * 32 + fm * 16 + rowA) * HRS + khA);
        const int rowB = (lane & 7) + ((lane >> 4) & 1) * 8;
        const int khB  = ((lane >> 3) & 1) * 16;
        #pragma unroll
        for (int p = 0; p < 4; p++)
            bAddr[p] = smb + H_B + (uint32_t)((wn * 64 + p * 16 + rowB) * HRS + khB);
    }

    float acc[2][8][4];
    #pragma unroll
    for (int i = 0; i < 2; i++)
        #pragma unroll
        for (int j = 0; j < 8; j++)
            #pragma unroll
            for (int e = 0; e < 4; e++) acc[i][j][e] = 0.f;

    load_chunk_h(sm, smb, 0, 0, t, g_q16, g_k16, aBase, bBase, true, w);
    CP_COMMIT();
    load_chunk_h(sm, smb, 1, 1, t, g_q16, g_k16, aBase, bBase, true, w);
    CP_COMMIT();

    #pragma unroll 1
    for (int c = 0; c < 32; c++) {
        CP_WAIT1();
        __syncthreads();
        compute_chunk_h((uint32_t)((c % 3) * H_BUFB), aAddr, bAddr, acc);
        const int cc = c + 2;
        if (cc < 32)
            load_chunk_h(sm, smb, cc, cc % 3, t, g_q16, g_k16, aBase, bBase, true, w);
        CP_COMMIT();
    }
    __syncthreads();

    // ---- stage acc -> stg [128][260] fp32 (row stride 1040B) ----
    float* stg = (float*)sm;
    #pragma unroll
    for (int fm = 0; fm < 2; fm++) {
        const int r0 = wm * 32 + fm * 16 + g;
        #pragma unroll
        for (int fn = 0; fn < 8; fn++) {
            const int c0 = wn * 64 + fn * 8 + tg * 2;
            stg[r0 * 260 + c0]           = acc[fm][fn][0];
            stg[r0 * 260 + c0 + 1]       = acc[fm][fn][1];
            stg[(r0 + 8) * 260 + c0]     = acc[fm][fn][2];
            stg[(r0 + 8) * 260 + c0 + 1] = acc[fm][fn][3];
        }
    }
    __syncthreads();

    // ---- softmax -> attn fp16 @ row start (in-place over stg rows) ----
    for (int rr = 0; rr < 8; rr++) {
        const int r = wid * 8 + rr;
        float vv[8];
        float mx = -FLT_MAX;
        #pragma unroll
        for (int u = 0; u < 8; u++) {
            int j = lane + u * 32;
            float sc = stg[r * 260 + j] * 0.03125f;
            vv[u] = (j <= r + 128) ? sc : -FLT_MAX;
            mx = fmaxf(mx, vv[u]);
        }
        #pragma unroll
        for (int off = 16; off; off >>= 1)
            mx = fmaxf(mx, __shfl_xor_sync(0xffffffffu, mx, off));
        float sum = 0.f;
        #pragma unroll
        for (int u = 0; u < 8; u++) {
            int j = lane + u * 32;
            vv[u] = (j <= r + 128) ? expf(vv[u] - mx) : 0.f;
            sum += vv[u];
        }
        #pragma unroll
        for (int off = 16; off; off >>= 1)
            sum += __shfl_xor_sync(0xffffffffu, sum, off);
        const float inv = 1.f / sum;
        __half* arow = (__half*)(sm + (size_t)r * 1040);
        #pragma unroll
        for (int u = 0; u < 8; u++) {
            int j = lane + u * 32;
            arow[j] = __float2half_rn(vv[u] * inv);
        }
    }
    __syncthreads();

    // ---- Phase B: ao = attn @ k2, 4 N-iters of 256 dims ----
    uint32_t aA[2], bT[4];
    {
        const int rowA = lane & 15;
        #pragma unroll
        for (int fm = 0; fm < 2; fm++)
            aA[fm] = smb + (uint32_t)((wm * 32 + fm * 16 + rowA) * 1040
                                      + ((lane >> 4) & 1) * 16);
        const int rowK = (lane & 7) + ((lane >> 3) & 1) * 8;
        const int dsel = ((lane >> 4) & 1) * 8;
        #pragma unroll
        for (int p = 0; p < 4; p++)
            bT[p] = smb + F_PV + (uint32_t)(rowK * 528
                                            + (wn * 64 + p * 16 + dsel) * 2);
    }

    #pragma unroll 1
    for (int niter = 0; niter < 4; niter++) {
        const int n0 = niter * 256;
        float acc2[2][8][4];
        #pragma unroll
        for (int i = 0; i < 2; i++)
            #pragma unroll
            for (int j = 0; j < 8; j++)
                #pragma unroll
                for (int e = 0; e < 4; e++) acc2[i][j][e] = 0.f;

        load_pv_chunk(smb, b, w, n0, 0, 0, t);
        CP_COMMIT();
        #pragma unroll 1
        for (int c = 0; c < 8; c++) {
            CP_WAIT0();
            __syncthreads();
            if (c < 7) {
                load_pv_chunk(smb, b, w, n0, c + 1, (c + 1) & 1, t);
                CP_COMMIT();
            }
            compute_pv((uint32_t)((c & 1) * F_SLOT), (uint32_t)(c * 64),
                       aA, bT, acc2);
        }

        // epilogue: store ao fp16
        #pragma unroll
        for (int fm = 0; fm < 2; fm++) {
            const int r0 = wm * 32 + fm * 16 + g;
            #pragma unroll
            for (int fn = 0; fn < 8; fn++) {
                const int c0 = n0 + wn * 64 + fn * 8 + tg * 2;
                #pragma unroll
                for (int half = 0; half < 2; half++) {
                    const int r = r0 + half * 8;
                    const size_t o = ((size_t)b * NN + (size_t)w * WW + r) * DD + c0;
                    *(__half2*)(g_ao16 + o) = __halves2half2(
                        __float2half_rn(acc2[fm][fn][half * 2]),
                        __float2half_rn(acc2[fm][fn][half * 2 + 1]));
                }
            }
        }
    }
}

// ---------------------------------------------------------------------------
// Converters — destinations are device globals referenced IN DEVICE CODE ONLY
// ---------------------------------------------------------------------------
__global__ void convert_x_kernel(const float* __restrict__ x)
{
    size_t i = ((size_t)blockIdx.x * blockDim.x + threadIdx.x) * 4;
    float4 v = *(const float4*)(x + i);
    g_x16[i + 0] = __float2half_rn(v.x);
    g_x16[i + 1] = __float2half_rn(v.y);
    g_x16[i + 2] = __float2half_rn(v.z);
    g_x16[i + 3] = __float2half_rn(v.w);
}

// dst[n][k] = src[k][n], fp16; which: 0 -> wqk, 1 -> wo.
__global__ void transpose_convert_w(const float* __restrict__ src, int ld, int which)
{
    __half* dh = (which == 0) ? g_w16qk : g_w16o;
    __shared__ float sh[32][33];
    const int n0 = blockIdx.x * 32, k0 = blockIdx.y * 32;
    const int tx = threadIdx.x, ty = threadIdx.y;
    #pragma unroll
    for (int i = 0; i < 4; i++)
        sh[ty + 8 * i][tx] = src[(size_t)(k0 + ty + 8 * i) * ld + n0 + tx];
    __syncthreads();
    #pragma unroll
    for (int i = 0; i < 4; i++) {
        float v = sh[tx][ty + 8 * i];
        int n = n0 + ty + 8 * i, k = k0 + tx;
        dh[(size_t)n * DD + k] = __float2half_rn(v);
    }
}

// ---------------------------------------------------------------------------
extern "C" void kernel_launch(void* const* d_in, const int* in_sizes, int n_in,
                              void* d_out, int out_size)
{
    (void)in_sizes; (void)n_in; (void)out_size;
    const float* x     = (const float*)d_in[0];   // [4,4096,1024]
    const float* w_qkv = (const float*)d_in[1];   // [1024,3072]
    const float* w_out = (const float*)d_in[2];   // [1024,1024]
    const float* b_out = (const float*)d_in[3];   // [1024]
    float* out = (float*)d_out;                   // [4,4096,1024]

    cudaFuncSetAttribute(mma_gemm,   cudaFuncAttributeMaxDynamicSharedMemorySize, SMEMB_H);
    cudaFuncSetAttribute(fused_attn, cudaFuncAttributeMaxDynamicSharedMemorySize, SMEMB_F);

    // 1) convert inputs to fp16
    convert_x_kernel<<<MTOT * DD / 1024, 256>>>(x);
    transpose_convert_w<<<dim3(64, 32), dim3(32, 8)>>>(w_qkv, 3072, 0);
    transpose_convert_w<<<dim3(32, 32), dim3(32, 8)>>>(w_out, 1024, 1);

    // 2) qk = x @ w_qkv[:, :2048]  (fp16) -> g_q16/g_k16
    mma_gemm<<<dim3(8, 128), NT, SMEMB_H>>>(0, nullptr, nullptr);

    // 3) fused attention (fp16; values==keys per reference bug)
    fused_attn<<<dim3(NWIN, BB), NT, SMEMB_F>>>();

    // 4) out = ao @ w_out + b_out  (fp16)
    mma_gemm<<<dim3(4, 128), NT, SMEMB_H>>>(3, out, b_out);
}